// round 7
// baseline (speedup 1.0000x reference)
#include <cuda_runtime.h>
#include <cuda_bf16.h>
#include <cstdint>

// ===========================================================================
// MultiHeadSelfAttention, sm_100 (mma.sync HMMA path everywhere).
//   s1: split x -> xa bf16 [8192 x 3072] ([hi|lo|hi])
//   s2/s3: transpose+split weights -> [N x 3K] bf16 ([hi|hi|lo])
//   k1: qkv GEMM (BK=64, 3-stage cp.async) -> split planes qhi/qlo,khi/klo,
//       vhiT/vloT. Q pre-scaled by 0.125*log2(e).
//   k2: flash attention, 256 thr (8 warps 2x4), double-buffered K/V,
//       chunk-remapped split products; writes augmented atta.
//   k3: out = atta @ wprojT^T + b_proj.
// ===========================================================================

#define EMBED   1024
#define HEADS   16
#define HDIM    64
#define BATCH   4
#define SEQ     2048
#define MROWS   (BATCH * SEQ)     // 8192
#define QKV_N   (3 * EMBED)       // 3072
#define KAUG    (3 * EMBED)       // 3072
#define NBH     (BATCH * HEADS)   // 64
#define QSC     (0.125f * 1.44269504f)

__device__ __nv_bfloat16  g_xa[(size_t)MROWS * KAUG];       // 48 MB
__device__ __nv_bfloat16  g_atta[(size_t)MROWS * KAUG];     // 48 MB
__device__ __nv_bfloat16  g_wqkvT[(size_t)QKV_N * KAUG];    // 18 MB
__device__ __nv_bfloat16  g_wprojT[(size_t)EMBED * KAUG];   //  6 MB
__device__ __nv_bfloat16  g_qhi[(size_t)NBH * SEQ * HDIM];
__device__ __nv_bfloat16  g_qlo[(size_t)NBH * SEQ * HDIM];
__device__ __nv_bfloat16  g_khi[(size_t)NBH * SEQ * HDIM];
__device__ __nv_bfloat16  g_klo[(size_t)NBH * SEQ * HDIM];
__device__ __nv_bfloat16  g_vhiT[(size_t)NBH * HDIM * SEQ];
__device__ __nv_bfloat16  g_vloT[(size_t)NBH * HDIM * SEQ];

// ---------------------------------------------------------------------------
// helpers
// ---------------------------------------------------------------------------
__device__ __forceinline__ uint32_t smem_u32(const void* p) {
    uint32_t a;
    asm("{ .reg .u64 t; cvta.to.shared.u64 t, %1; cvt.u32.u64 %0, t; }"
        : "=r"(a) : "l"(p));
    return a;
}
__device__ __forceinline__ void ldsm_x4(uint32_t& r0, uint32_t& r1,
                                        uint32_t& r2, uint32_t& r3, uint32_t addr) {
    asm volatile("ldmatrix.sync.aligned.m8n8.x4.shared.b16 {%0,%1,%2,%3}, [%4];"
                 : "=r"(r0), "=r"(r1), "=r"(r2), "=r"(r3) : "r"(addr));
}
__device__ __forceinline__ void mma_bf16(float* c, uint32_t a0, uint32_t a1,
                                         uint32_t a2, uint32_t a3,
                                         uint32_t b0, uint32_t b1) {
    asm volatile(
        "mma.sync.aligned.m16n8k16.row.col.f32.bf16.bf16.f32 "
        "{%0,%1,%2,%3}, {%4,%5,%6,%7}, {%8,%9}, {%0,%1,%2,%3};"
        : "+f"(c[0]), "+f"(c[1]), "+f"(c[2]), "+f"(c[3])
        : "r"(a0), "r"(a1), "r"(a2), "r"(a3), "r"(b0), "r"(b1));
}
#define CP_ASYNC16(smem, gptr) \
    asm volatile("cp.async.cg.shared.global [%0], [%1], 16;" :: "r"(smem), "l"(gptr))
#define CP_COMMIT() asm volatile("cp.async.commit_group;" ::: "memory")
#define CP_WAIT1()  asm volatile("cp.async.wait_group 1;" ::: "memory")

// 128B-row tile (8 chunks/row): chunk' = chunk ^ (row & 7)
__device__ __forceinline__ uint32_t goff(int r, int c) {
    return (uint32_t)(r * 128 + ((c ^ (r & 7)) << 4));
}
// 256B-row tile (16 chunks/row): chunk' = chunk ^ (row & 7)  (within 8-chunk half)
__device__ __forceinline__ uint32_t foff(int r, int c) {
    return (uint32_t)(r * 256 + ((c ^ (r & 7)) << 4));
}

__device__ __forceinline__ void split_hl(float v, __nv_bfloat16& hi, __nv_bfloat16& lo) {
    hi = __float2bfloat16_rn(v);
    lo = __float2bfloat16_rn(v - __bfloat162float(hi));
}
__device__ __forceinline__ uint32_t pack2bf(__nv_bfloat16 a, __nv_bfloat16 b) {
    __nv_bfloat162 p(a, b);
    return *reinterpret_cast<uint32_t*>(&p);
}

// ---------------------------------------------------------------------------
// s1: split x -> xa [hi | lo | hi]
// ---------------------------------------------------------------------------
__global__ void __launch_bounds__(256)
split_x_kernel(const float* __restrict__ x, __nv_bfloat16* __restrict__ xa)
{
    const int row = blockIdx.x;
    const int c = threadIdx.x * 4;
    float4 v = *(const float4*)(x + (size_t)row * EMBED + c);
    __nv_bfloat16 h0,h1,h2,h3,l0,l1,l2,l3;
    split_hl(v.x, h0, l0); split_hl(v.y, h1, l1);
    split_hl(v.z, h2, l2); split_hl(v.w, h3, l3);
    const size_t o = (size_t)row * KAUG + c;
    uint2 uh; uh.x = pack2bf(h0,h1); uh.y = pack2bf(h2,h3);
    uint2 ul; ul.x = pack2bf(l0,l1); ul.y = pack2bf(l2,l3);
    *(uint2*)(xa + o)           = uh;
    *(uint2*)(xa + o + EMBED)   = ul;
    *(uint2*)(xa + o + 2*EMBED) = uh;
}

// ---------------------------------------------------------------------------
// s2/s3: W [K x N] fp32 -> Bp [N x 3K] bf16 ([hi | hi | lo])
// ---------------------------------------------------------------------------
__global__ void __launch_bounds__(256)
transpose_split_kernel(const float* __restrict__ W, __nv_bfloat16* __restrict__ Bp,
                       int K, int N)
{
    __shared__ float t[32][33];
    const int n0 = blockIdx.x * 32, k0 = blockIdx.y * 32;
    const int tx = threadIdx.x, ty = threadIdx.y;
    #pragma unroll
    for (int i = 0; i < 4; ++i)
        t[ty + 8*i][tx] = W[(size_t)(k0 + ty + 8*i) * N + n0 + tx];
    __syncthreads();
    #pragma unroll
    for (int i = 0; i < 4; ++i) {
        const int n = ty + 8*i;
        float v = t[tx][n];
        __nv_bfloat16 hi, lo;
        split_hl(v, hi, lo);
        const size_t ro = (size_t)(n0 + n) * (3*K);
        Bp[ro + k0 + tx]       = hi;
        Bp[ro + K + k0 + tx]   = hi;
        Bp[ro + 2*K + k0 + tx] = lo;
    }
}

// ---------------------------------------------------------------------------
// HMMA GEMM: 128x128x64 tile, 8 warps (2x4), 3-stage cp.async pipeline.
// dyn smem = 3 stages x (16KB A + 16KB B) = 96KB.
// MODE 0: C = A@B^T + bias.  MODE 1: qkv epilogue -> split planes.
// ---------------------------------------------------------------------------
#define GEMM_SMEM (3 * 32768)

template<int MODE>
__global__ void __launch_bounds__(256)
mma_gemm_kernel(const __nv_bfloat16* __restrict__ A, const __nv_bfloat16* __restrict__ B,
                const float* __restrict__ bias, float* __restrict__ C,
                __nv_bfloat16* __restrict__ qh, __nv_bfloat16* __restrict__ ql,
                __nv_bfloat16* __restrict__ kh, __nv_bfloat16* __restrict__ kl,
                __nv_bfloat16* __restrict__ vh, __nv_bfloat16* __restrict__ vl,
                int M, int N, int K)
{
    extern __shared__ __align__(1024) uint8_t dsm[];

    const int tid  = threadIdx.x;
    const int wid  = tid >> 5;
    const int lane = tid & 31;
    const int bx = blockIdx.x, by = blockIdx.y;
    const int warp_m = wid & 1;
    const int warp_n = wid >> 1;
    const uint32_t sbase = smem_u32(dsm);

    const size_t Ks = (size_t)K;
    const __nv_bfloat16* Ab = A + (size_t)(by * 128) * Ks;
    const __nv_bfloat16* Bb = B + (size_t)(bx * 128) * Ks;

    // load geometry: 1024 chunks per matrix per stage; thread does 4 A + 4 B,
    // rows r0 + 32*j (swizzle invariant: (r+32)&7 == r&7)
    const int r0 = tid >> 3, c0 = tid & 7;
    const __nv_bfloat16* Ag0 = Ab + (size_t)r0 * Ks + c0 * 8;
    const __nv_bfloat16* Bg0 = Bb + (size_t)r0 * Ks + c0 * 8;
    const size_t rs32 = (size_t)32 * Ks;
    const uint32_t sA0 = goff(r0, c0);

    auto load_stage = [&](int kt, uint32_t sbuf) {
        const size_t k0 = (size_t)kt * 64;
        #pragma unroll
        for (int j = 0; j < 4; ++j) {
            CP_ASYNC16(sbuf + sA0 + j*4096,         Ag0 + k0 + j*rs32);
            CP_ASYNC16(sbuf + 16384 + sA0 + j*4096, Bg0 + k0 + j*rs32);
        }
    };

    // hoisted ldsm row parts; column xor computed inline
    const int hi = lane >> 4;
    uint32_t arow[4]; int axr[4];
    #pragma unroll
    for (int mf = 0; mf < 4; ++mf) {
        const int r = warp_m * 64 + mf * 16 + (lane & 15);
        arow[mf] = (uint32_t)(r * 128);  axr[mf] = r & 7;
    }
    uint32_t brow[2]; int bxr[2];
    #pragma unroll
    for (int np = 0; np < 2; ++np) {
        const int r = warp_n * 32 + np * 16 + (lane & 15);
        brow[np] = (uint32_t)(16384 + r * 128);  bxr[np] = r & 7;
    }

    float acc[4][4][4] = {};
    const int T = K >> 6;      // 48

    load_stage(0, sbase);            CP_COMMIT();
    load_stage(1, sbase + 32768);    CP_COMMIT();

    int cb = 0, lb = 2;
    for (int t = 0; t < T; ++t) {
        CP_WAIT1();
        __syncthreads();

        const uint32_t st = sbase + (uint32_t)cb * 32768;
        #pragma unroll
        for (int ks = 0; ks < 4; ++ks) {
            const int cc = ks * 2 + hi;
            uint32_t a[4][4];
            #pragma unroll
            for (int mf = 0; mf < 4; ++mf)
                ldsm_x4(a[mf][0], a[mf][1], a[mf][2], a[mf][3],
                        st + arow[mf] + (uint32_t)((cc ^ axr[mf]) << 4));
            uint32_t b[2][4];
            #pragma unroll
            for (int np = 0; np < 2; ++np)
                ldsm_x4(b[np][0], b[np][1], b[np][2], b[np][3],
                        st + brow[np] + (uint32_t)((cc ^ bxr[np]) << 4));
            #pragma unroll
            for (int mf = 0; mf < 4; ++mf)
                #pragma unroll
                for (int nf = 0; nf < 4; ++nf) {
                    const int np = nf >> 1, hl = nf & 1;
                    mma_bf16(acc[mf][nf], a[mf][0], a[mf][1], a[mf][2], a[mf][3],
                             b[np][0 + hl], b[np][2 + hl]);
                }
        }

        if (t + 2 < T) load_stage(t + 2, sbase + (uint32_t)lb * 32768);
        CP_COMMIT();
        cb = (cb + 1 == 3) ? 0 : cb + 1;
        lb = (lb + 1 == 3) ? 0 : lb + 1;
    }

    const int g  = lane >> 2;
    const int cl = (lane & 3) * 2;
    #pragma unroll
    for (int mf = 0; mf < 4; ++mf) {
        const int mrow = by * 128 + warp_m * 64 + mf * 16 + g;
        #pragma unroll
        for (int nf = 0; nf < 4; ++nf) {
            const int col = bx * 128 + warp_n * 32 + nf * 8 + cl;
            const float b0 = bias[col], b1 = bias[col + 1];
            float v[4] = { acc[mf][nf][0] + b0, acc[mf][nf][1] + b1,
                           acc[mf][nf][2] + b0, acc[mf][nf][3] + b1 };
            if constexpr (MODE == 0) {
                *(float2*)(C + (size_t)mrow * N + col)       = make_float2(v[0], v[1]);
                *(float2*)(C + (size_t)(mrow + 8) * N + col) = make_float2(v[2], v[3]);
            } else {
                const int which = col >> 10;           // 0=q 1=k 2=v
                const int h = (col >> 6) & 15;
                const int d = col & 63;
                const int bb = mrow >> 11;
                const int n0 = mrow & 2047;
                if (which == 0) { v[0]*=QSC; v[1]*=QSC; v[2]*=QSC; v[3]*=QSC; }
                #pragma unroll
                for (int rr = 0; rr < 2; ++rr) {
                    const int n = n0 + rr * 8;
                    __nv_bfloat16 h0,l0,h1,l1;
                    split_hl(v[rr*2+0], h0, l0);
                    split_hl(v[rr*2+1], h1, l1);
                    if (which < 2) {
                        const size_t base = (size_t)(bb*16 + h) * (SEQ*HDIM)
                                          + (size_t)n * HDIM + d;
                        __nv_bfloat16* PH = which ? kh : qh;
                        __nv_bfloat16* PL = which ? kl : ql;
                        *(uint32_t*)(PH + base) = pack2bf(h0, h1);
                        *(uint32_t*)(PL + base) = pack2bf(l0, l1);
                    } else {
                        const size_t base = (size_t)(bb*16 + h) * (SEQ*HDIM)
                                          + (size_t)d * SEQ + n;
                        vh[base]       = h0;  vh[base + SEQ] = h1;
                        vl[base]       = l0;  vl[base + SEQ] = l1;
                    }
                }
            }
        }
    }
}

// ---------------------------------------------------------------------------
// k2: flash attention on HMMA, 256 thr (8 warps, warpM x warpN = 2 x 4),
// double-buffered K/V. Warp tile 32x16.
// smem: Qa 16K | Ka[2] 32K | Va[2] 32K | Pa 16K | stats 2.5K = 100864 B.
// ---------------------------------------------------------------------------
#define FLASH_SMEM (98304 + 2560)

__global__ void __launch_bounds__(256)
flash_mma_kernel(const __nv_bfloat16* __restrict__ qhi, const __nv_bfloat16* __restrict__ qlo,
                 const __nv_bfloat16* __restrict__ khi, const __nv_bfloat16* __restrict__ klo,
                 const __nv_bfloat16* __restrict__ vhiT, const __nv_bfloat16* __restrict__ vloT,
                 __nv_bfloat16* __restrict__ atta)
{
    extern __shared__ __align__(1024) uint8_t fsm[];
    uint8_t* Pa_c = fsm + 81920;
    float* pmax = (float*)(fsm + 98304);     // [4][64]
    float* psum = pmax + 256;                // [4][64]
    float* m_s  = psum + 256;                // [64]
    float* l_s  = m_s + 64;                  // [64]

    const uint32_t sbase = smem_u32(fsm);
    const uint32_t qa_u  = sbase;
    const uint32_t ka_u0 = sbase + 16384;    // + buf*16384
    const uint32_t va_u0 = sbase + 49152;    // + buf*16384
    const uint32_t pa_u  = sbase + 81920;

    const int tid  = threadIdx.x;
    const int wid  = tid >> 5;
    const int lane = tid & 31;
    const int warpM = wid >> 2;      // 0..1 (query half)
    const int warpN = wid & 3;       // 0..3 (key/dim 16-segment)
    const int g  = lane >> 2;
    const int qd = lane & 3;

    const int qt = blockIdx.x, bh = blockIdx.y;
    const int q0 = qt * 64;

    // Q load
    {
        const size_t qbase = ((size_t)bh * SEQ + q0) * HDIM;
        for (int i = tid; i < 1024; i += 256) {
            const int r = i >> 4, c = i & 15;
            CP_ASYNC16(qa_u + foff(r, c),
                       (c < 8 ? qhi : qlo) + qbase + r * HDIM + (c & 7) * 8);
        }
        CP_COMMIT();
    }

    auto load_kv = [&](int kt, int buf) {
        const size_t kbase = ((size_t)bh * SEQ + kt * 64) * HDIM;
        const uint32_t ka = ka_u0 + buf * 16384, va = va_u0 + buf * 16384;
        for (int i = tid; i < 1024; i += 256) {
            const int r = i >> 4, c = i & 15;
            CP_ASYNC16(ka + foff(r, c),
                       (c < 8 ? khi : klo) + kbase + r * HDIM + (c & 7) * 8);
            CP_ASYNC16(va + foff(r, c),
                       (c < 8 ? vhiT : vloT) + (size_t)(bh * HDIM + r) * SEQ
                                             + kt * 64 + (c & 7) * 8);
        }
    };

    load_kv(0, 0); CP_COMMIT();
    if (tid < 64) { m_s[tid] = -1e30f; l_s[tid] = 0.f; }

    const int AU[12] = {0,1,2,3, 4,5,6,7, 0,1,2,3};
    const int BU[12] = {0,1,2,3, 0,1,2,3, 4,5,6,7};

    float oacc[2][2][4] = {};

    for (int kt = 0; kt < 32; ++kt) {
        const int buf = kt & 1;
        __syncthreads();              // (a) prior iter done (other buf, Pa free)
        if (kt + 1 < 32) load_kv(kt + 1, buf ^ 1);
        CP_COMMIT();
        CP_WAIT1();                   // KV(kt) landed
        __syncthreads();              // (b) everyone's KV(kt) visible

        const uint32_t ka_u = ka_u0 + buf * 16384;
        const uint32_t va_u = va_u0 + buf * 16384;

        // ---- S = Qa @ Ka^T ----
        float sacc[2][2][4] = {};
        #pragma unroll
        for (int s = 0; s < 12; ++s) {
            uint32_t a[2][4], bfr[4];
            #pragma unroll
            for (int m = 0; m < 2; ++m)
                ldsm_x4(a[m][0], a[m][1], a[m][2], a[m][3],
                        qa_u + foff(warpM*32 + m*16 + (lane & 15), 2*AU[s] + (lane >> 4)));
            ldsm_x4(bfr[0], bfr[1], bfr[2], bfr[3],
                    ka_u + foff(warpN*16 + (lane & 15), 2*BU[s] + (lane >> 4)));
            #pragma unroll
            for (int m = 0; m < 2; ++m)
                #pragma unroll
                for (int nf = 0; nf < 2; ++nf)
                    mma_bf16(sacc[m][nf], a[m][0], a[m][1], a[m][2], a[m][3],
                             bfr[nf], bfr[2 + nf]);
        }

        // ---- softmax ----
        float tmax[2][2];
        #pragma unroll
        for (int m = 0; m < 2; ++m)
            #pragma unroll
            for (int gg = 0; gg < 2; ++gg)
                tmax[m][gg] = fmaxf(fmaxf(sacc[m][0][gg*2], sacc[m][0][gg*2+1]),
                                    fmaxf(sacc[m][1][gg*2], sacc[m][1][gg*2+1]));
        #pragma unroll
        for (int o = 1; o <= 2; o <<= 1)
            #pragma unroll
            for (int m = 0; m < 2; ++m)
                #pragma unroll
                for (int gg = 0; gg < 2; ++gg)
                    tmax[m][gg] = fmaxf(tmax[m][gg],
                                        __shfl_xor_sync(0xffffffffu, tmax[m][gg], o));
        if (qd == 0)
            #pragma unroll
            for (int m = 0; m < 2; ++m)
                #pragma unroll
                for (int gg = 0; gg < 2; ++gg)
                    pmax[warpN*64 + warpM*32 + m*16 + g + gg*8] = tmax[m][gg];
        __syncthreads();   // b1

        float corr[2][2], tsum[2][2];
        #pragma unroll
        for (int m = 0; m < 2; ++m)
            #pragma unroll
            for (int gg = 0; gg < 2; ++gg) {
                const int r = warpM*32 + m*16 + g + gg*8;
                const float mx = fmaxf(fmaxf(pmax[r], pmax[64 + r]),
                                       fmaxf(pmax[128 + r], pmax[192 + r]));
                const float mo = m_s[r];
                const float mn = fmaxf(mo, mx);
                corr[m][gg] = exp2f(mo - mn);
                float sum = 0.f;
                #pragma unroll
                for (int nf = 0; nf < 2; ++nf) {
                    const float p0 = exp2f(sacc[m][nf][gg*2]   - mn);
                    const float p1 = exp2f(sacc[m][nf][gg*2+1] - mn);
                    sum += p0 + p1;
                    __nv_bfloat16 h0,l0,h1,l1;
                    split_hl(p0, h0, l0);
                    split_hl(p1, h1, l1);
                    const int chunk = warpN*2 + nf;
                    *(uint32_t*)(Pa_c + foff(r, chunk)     + qd*4) = pack2bf(h0, h1);
                    *(uint32_t*)(Pa_c + foff(r, chunk + 8) + qd*4) = pack2bf(l0, l1);
                }
                tsum[m][gg] = sum;
            }
        #pragma unroll
        for (int o = 1; o <= 2; o <<= 1)
            #pragma unroll
            for (int m = 0; m < 2; ++m)
                #pragma unroll
                for (int gg = 0; gg < 2; ++gg)
                    tsum[m][gg] += __shfl_xor_sync(0xffffffffu, tsum[m][gg], o);
        if (qd == 0)
            #pragma unroll
            for (int m = 0; m < 2; ++m)
                #pragma unroll
                for (int gg = 0; gg < 2; ++gg)
                    psum[warpN*64 + warpM*32 + m*16 + g + gg*8] = tsum[m][gg];
        #pragma unroll
        for (int m = 0; m < 2; ++m)
            #pragma unroll
            for (int nf = 0; nf < 2; ++nf) {
                oacc[m][nf][0] *= corr[m][0];
                oacc[m][nf][1] *= corr[m][0];
                oacc[m][nf][2] *= corr[m][1];
                oacc[m][nf][3] *= corr[m][1];
            }
        __syncthreads();   // b2: Pa + psum visible

        if (tid < 64) {
            const float mo = m_s[tid];
            const float mx = fmaxf(fmaxf(pmax[tid], pmax[64 + tid]),
                                   fmaxf(pmax[128 + tid], pmax[192 + tid]));
            const float mn = fmaxf(mo, mx);
            const float cr = exp2f(mo - mn);
            l_s[tid] = l_s[tid] * cr + psum[tid] + psum[64 + tid]
                                     + psum[128 + tid] + psum[192 + tid];
            m_s[tid] = mn;
        }

        // ---- O += Pa @ Va^T ----
        #pragma unroll
        for (int s = 0; s < 12; ++s) {
            uint32_t a[2][4], bfr[4];
            #pragma unroll
            for (int m = 0; m < 2; ++m)
                ldsm_x4(a[m][0], a[m][1], a[m][2], a[m][3],
                        pa_u + foff(warpM*32 + m*16 + (lane & 15), 2*AU[s] + (lane >> 4)));
            ldsm_x4(bfr[0], bfr[1], bfr[2], bfr[3],
                    va_u + foff(warpN*16 + (lane & 15), 2*BU[s] + (lane >> 4)));
            #pragma unroll
            for (int m = 0; m < 2; ++m)
                #pragma unroll
                for (int nf = 0; nf < 2; ++nf)
                    mma_bf16(oacc[m][nf], a[m][0], a[m][1], a[m][2], a[m][3],
                             bfr[nf], bfr[2 + nf]);
        }
    }
    __syncthreads();

    const int b_ = bh >> 4, h = bh & 15;
    float inv[2][2];
    #pragma unroll
    for (int m = 0; m < 2; ++m)
        #pragma unroll
        for (int gg = 0; gg < 2; ++gg)
            inv[m][gg] = 1.f / l_s[warpM*32 + m*16 + g + gg*8];

    #pragma unroll
    for (int m = 0; m < 2; ++m)
        #pragma unroll
        for (int nf = 0; nf < 2; ++nf) {
            const int colL = warpN*16 + nf*8 + qd*2;
            #pragma unroll
            for (int gg = 0; gg < 2; ++gg) {
                const int r = warpM*32 + m*16 + g + gg*8;
                const float v0 = oacc[m][nf][gg*2]   * inv[m][gg];
                const float v1 = oacc[m][nf][gg*2+1] * inv[m][gg];
                __nv_bfloat16 h0,l0,h1,l1;
                split_hl(v0, h0, l0);
                split_hl(v1, h1, l1);
                const size_t ro = (size_t)(b_*SEQ + q0 + r) * KAUG + h*64 + colL;
                *(uint32_t*)(atta + ro)            = pack2bf(h0, h1);
                *(uint32_t*)(atta + ro + EMBED)    = pack2bf(l0, l1);
                *(uint32_t*)(atta + ro + 2*EMBED)  = pack2bf(h0, h1);
            }
        }
}

// ---------------------------------------------------------------------------
// Launch
// ---------------------------------------------------------------------------
extern "C" void kernel_launch(void* const* d_in, const int* in_sizes, int n_in,
                              void* d_out, int out_size)
{
    const float* x      = (const float*)d_in[0];
    const float* w_qkv  = (const float*)d_in[1];
    const float* b_qkv  = (const float*)d_in[2];
    const float* w_proj = (const float*)d_in[3];
    const float* b_proj = (const float*)d_in[4];
    float* out = (float*)d_out;

    __nv_bfloat16 *xa, *atta, *wqkvT, *wprojT, *qh, *ql, *kh, *kl, *vh, *vl;
    cudaGetSymbolAddress((void**)&xa,     g_xa);
    cudaGetSymbolAddress((void**)&atta,   g_atta);
    cudaGetSymbolAddress((void**)&wqkvT,  g_wqkvT);
    cudaGetSymbolAddress((void**)&wprojT, g_wprojT);
    cudaGetSymbolAddress((void**)&qh,     g_qhi);
    cudaGetSymbolAddress((void**)&ql,     g_qlo);
    cudaGetSymbolAddress((void**)&kh,     g_khi);
    cudaGetSymbolAddress((void**)&kl,     g_klo);
    cudaGetSymbolAddress((void**)&vh,     g_vhiT);
    cudaGetSymbolAddress((void**)&vl,     g_vloT);

    cudaFuncSetAttribute(mma_gemm_kernel<1>,
                         cudaFuncAttributeMaxDynamicSharedMemorySize, GEMM_SMEM);
    cudaFuncSetAttribute(mma_gemm_kernel<0>,
                         cudaFuncAttributeMaxDynamicSharedMemorySize, GEMM_SMEM);
    cudaFuncSetAttribute(flash_mma_kernel,
                         cudaFuncAttributeMaxDynamicSharedMemorySize, FLASH_SMEM);

    split_x_kernel<<<MROWS, 256>>>(x, xa);
    transpose_split_kernel<<<dim3(QKV_N/32, EMBED/32), dim3(32,8)>>>(w_qkv, wqkvT, EMBED, QKV_N);
    transpose_split_kernel<<<dim3(EMBED/32, EMBED/32), dim3(32,8)>>>(w_proj, wprojT, EMBED, EMBED);

    mma_gemm_kernel<1><<<dim3(QKV_N/128, MROWS/128), 256, GEMM_SMEM>>>(
        xa, wqkvT, b_qkv, nullptr, qh, ql, kh, kl, vh, vl, MROWS, QKV_N, KAUG);

    flash_mma_kernel<<<dim3(SEQ/64, NBH), 256, FLASH_SMEM>>>(qh, ql, kh, kl, vh, vl, atta);

    mma_gemm_kernel<0><<<dim3(EMBED/128, MROWS/128), 256, GEMM_SMEM>>>(
        atta, wprojT, b_proj, out, nullptr, nullptr, nullptr, nullptr, nullptr, nullptr,
        MROWS, EMBED, KAUG);
}

// round 10
// speedup vs baseline: 1.0734x; 1.0734x over previous
#include <cuda_runtime.h>
#include <cuda_bf16.h>
#include <cstdint>

// ===========================================================================
// MultiHeadSelfAttention, sm_100 (mma.sync HMMA path everywhere).
//   s1: split x -> xa bf16 [8192 x 3072] ([hi|lo|hi])
//   s2/s3: transpose+split weights -> [N x 3K] bf16 ([hi|hi|lo])
//   k1: qkv GEMM (BK=32, 4-stage cp.async) -> split planes. Q pre-scaled.
//   k2: flash attention, 128 thr, double-buffered K/V, operand-reuse-ordered
//       split products (no register caching) -> augmented atta.
//   k3: out = atta @ wprojT^T + b_proj.
// ===========================================================================

#define EMBED   1024
#define HEADS   16
#define HDIM    64
#define BATCH   4
#define SEQ     2048
#define MROWS   (BATCH * SEQ)     // 8192
#define QKV_N   (3 * EMBED)       // 3072
#define KAUG    (3 * EMBED)       // 3072
#define NBH     (BATCH * HEADS)   // 64
#define QSC     (0.125f * 1.44269504f)

__device__ __nv_bfloat16  g_xa[(size_t)MROWS * KAUG];       // 48 MB
__device__ __nv_bfloat16  g_atta[(size_t)MROWS * KAUG];     // 48 MB
__device__ __nv_bfloat16  g_wqkvT[(size_t)QKV_N * KAUG];    // 18 MB
__device__ __nv_bfloat16  g_wprojT[(size_t)EMBED * KAUG];   //  6 MB
__device__ __nv_bfloat16  g_qhi[(size_t)NBH * SEQ * HDIM];
__device__ __nv_bfloat16  g_qlo[(size_t)NBH * SEQ * HDIM];
__device__ __nv_bfloat16  g_khi[(size_t)NBH * SEQ * HDIM];
__device__ __nv_bfloat16  g_klo[(size_t)NBH * SEQ * HDIM];
__device__ __nv_bfloat16  g_vhiT[(size_t)NBH * HDIM * SEQ];
__device__ __nv_bfloat16  g_vloT[(size_t)NBH * HDIM * SEQ];

// ---------------------------------------------------------------------------
// helpers
// ---------------------------------------------------------------------------
__device__ __forceinline__ uint32_t smem_u32(const void* p) {
    uint32_t a;
    asm("{ .reg .u64 t; cvta.to.shared.u64 t, %1; cvt.u32.u64 %0, t; }"
        : "=r"(a) : "l"(p));
    return a;
}
__device__ __forceinline__ void ldsm_x4(uint32_t& r0, uint32_t& r1,
                                        uint32_t& r2, uint32_t& r3, uint32_t addr) {
    asm volatile("ldmatrix.sync.aligned.m8n8.x4.shared.b16 {%0,%1,%2,%3}, [%4];"
                 : "=r"(r0), "=r"(r1), "=r"(r2), "=r"(r3) : "r"(addr));
}
__device__ __forceinline__ void mma_bf16(float* c, uint32_t a0, uint32_t a1,
                                         uint32_t a2, uint32_t a3,
                                         uint32_t b0, uint32_t b1) {
    asm volatile(
        "mma.sync.aligned.m16n8k16.row.col.f32.bf16.bf16.f32 "
        "{%0,%1,%2,%3}, {%4,%5,%6,%7}, {%8,%9}, {%0,%1,%2,%3};"
        : "+f"(c[0]), "+f"(c[1]), "+f"(c[2]), "+f"(c[3])
        : "r"(a0), "r"(a1), "r"(a2), "r"(a3), "r"(b0), "r"(b1));
}
#define CP_ASYNC16(smem, gptr) \
    asm volatile("cp.async.cg.shared.global [%0], [%1], 16;" :: "r"(smem), "l"(gptr))
#define CP_COMMIT() asm volatile("cp.async.commit_group;" ::: "memory")
#define CP_WAIT0()  asm volatile("cp.async.wait_group 0;" ::: "memory")
#define CP_WAIT1()  asm volatile("cp.async.wait_group 1;" ::: "memory")
#define CP_WAIT2()  asm volatile("cp.async.wait_group 2;" ::: "memory")

// GEMM tile (64B rows): chunk' = chunk ^ ((row>>1)&3)
__device__ __forceinline__ uint32_t tile_off(int r, int c) {
    return (uint32_t)(r * 64 + ((c ^ ((r >> 1) & 3)) << 4));
}
// Flash tile (256B rows, 16 chunks): chunk' = chunk ^ (row & 7)
__device__ __forceinline__ uint32_t foff(int r, int c) {
    return (uint32_t)(r * 256 + ((c ^ (r & 7)) << 4));
}

__device__ __forceinline__ void split_hl(float v, __nv_bfloat16& hi, __nv_bfloat16& lo) {
    hi = __float2bfloat16_rn(v);
    lo = __float2bfloat16_rn(v - __bfloat162float(hi));
}
__device__ __forceinline__ uint32_t pack2bf(__nv_bfloat16 a, __nv_bfloat16 b) {
    __nv_bfloat162 p(a, b);
    return *reinterpret_cast<uint32_t*>(&p);
}

// ---------------------------------------------------------------------------
// s1: split x -> xa [hi | lo | hi]
// ---------------------------------------------------------------------------
__global__ void __launch_bounds__(256)
split_x_kernel(const float* __restrict__ x, __nv_bfloat16* __restrict__ xa)
{
    const int row = blockIdx.x;
    const int c = threadIdx.x * 4;
    float4 v = *(const float4*)(x + (size_t)row * EMBED + c);
    __nv_bfloat16 h0,h1,h2,h3,l0,l1,l2,l3;
    split_hl(v.x, h0, l0); split_hl(v.y, h1, l1);
    split_hl(v.z, h2, l2); split_hl(v.w, h3, l3);
    const size_t o = (size_t)row * KAUG + c;
    uint2 uh; uh.x = pack2bf(h0,h1); uh.y = pack2bf(h2,h3);
    uint2 ul; ul.x = pack2bf(l0,l1); ul.y = pack2bf(l2,l3);
    *(uint2*)(xa + o)           = uh;
    *(uint2*)(xa + o + EMBED)   = ul;
    *(uint2*)(xa + o + 2*EMBED) = uh;
}

// ---------------------------------------------------------------------------
// s2/s3: W [K x N] fp32 -> Bp [N x 3K] bf16 ([hi | hi | lo])
// ---------------------------------------------------------------------------
__global__ void __launch_bounds__(256)
transpose_split_kernel(const float* __restrict__ W, __nv_bfloat16* __restrict__ Bp,
                       int K, int N)
{
    __shared__ float t[32][33];
    const int n0 = blockIdx.x * 32, k0 = blockIdx.y * 32;
    const int tx = threadIdx.x, ty = threadIdx.y;
    #pragma unroll
    for (int i = 0; i < 4; ++i)
        t[ty + 8*i][tx] = W[(size_t)(k0 + ty + 8*i) * N + n0 + tx];
    __syncthreads();
    #pragma unroll
    for (int i = 0; i < 4; ++i) {
        const int n = ty + 8*i;
        float v = t[tx][n];
        __nv_bfloat16 hi, lo;
        split_hl(v, hi, lo);
        const size_t ro = (size_t)(n0 + n) * (3*K);
        Bp[ro + k0 + tx]       = hi;
        Bp[ro + K + k0 + tx]   = hi;
        Bp[ro + 2*K + k0 + tx] = lo;
    }
}

// ---------------------------------------------------------------------------
// HMMA GEMM (round-6 best): 128x128x32 tile, 8 warps (2x4), 4-stage cp.async.
// dyn smem = 4 x 16KB = 64KB.
// MODE 0: C = A@B^T + bias.  MODE 1: qkv epilogue -> split planes.
// ---------------------------------------------------------------------------
#define GEMM_SMEM 65536

template<int MODE>
__global__ void __launch_bounds__(256)
mma_gemm_kernel(const __nv_bfloat16* __restrict__ A, const __nv_bfloat16* __restrict__ B,
                const float* __restrict__ bias, float* __restrict__ C,
                __nv_bfloat16* __restrict__ qh, __nv_bfloat16* __restrict__ ql,
                __nv_bfloat16* __restrict__ kh, __nv_bfloat16* __restrict__ kl,
                __nv_bfloat16* __restrict__ vh, __nv_bfloat16* __restrict__ vl,
                int M, int N, int K)
{
    extern __shared__ __align__(1024) uint8_t dsm[];

    const int tid  = threadIdx.x;
    const int wid  = tid >> 5;
    const int lane = tid & 31;
    const int bx = blockIdx.x, by = blockIdx.y;
    const int warp_m = wid & 1;
    const int warp_n = wid >> 1;
    const uint32_t sbase = smem_u32(dsm);

    const size_t Ks = (size_t)K;
    const __nv_bfloat16* Ab = A + (size_t)(by * 128) * Ks;
    const __nv_bfloat16* Bb = B + (size_t)(bx * 128) * Ks;

    const int lr0 = tid >> 2,         lc0 = tid & 3;
    const int lr1 = (tid + 256) >> 2, lc1 = (tid + 256) & 3;
    const __nv_bfloat16* Ag0 = Ab + (size_t)lr0 * Ks + lc0 * 8;
    const __nv_bfloat16* Ag1 = Ab + (size_t)lr1 * Ks + lc1 * 8;
    const __nv_bfloat16* Bg0 = Bb + (size_t)lr0 * Ks + lc0 * 8;
    const __nv_bfloat16* Bg1 = Bb + (size_t)lr1 * Ks + lc1 * 8;
    const uint32_t sA0 = tile_off(lr0, lc0), sA1 = tile_off(lr1, lc1);

    auto load_stage = [&](int kt, int st) {
        const int k0 = kt * 32;
        const uint32_t s = sbase + st * 16384;
        CP_ASYNC16(s + sA0,        Ag0 + k0);
        CP_ASYNC16(s + sA1,        Ag1 + k0);
        CP_ASYNC16(s + 8192 + sA0, Bg0 + k0);
        CP_ASYNC16(s + 8192 + sA1, Bg1 + k0);
    };

    uint32_t aoff[2][4], boff[2][2];
    #pragma unroll
    for (int ks = 0; ks < 2; ++ks) {
        #pragma unroll
        for (int mf = 0; mf < 4; ++mf)
            aoff[ks][mf] = tile_off(warp_m * 64 + mf * 16 + (lane & 15),
                                    ks * 2 + (lane >> 4));
        #pragma unroll
        for (int np = 0; np < 2; ++np)
            boff[ks][np] = 8192 + tile_off(warp_n * 32 + np * 16 + (lane & 15),
                                           ks * 2 + (lane >> 4));
    }

    float acc[4][4][4] = {};
    const int T = K >> 5;      // 96

    load_stage(0, 0); CP_COMMIT();
    load_stage(1, 1); CP_COMMIT();
    load_stage(2, 2); CP_COMMIT();

    for (int t = 0; t < T; ++t) {
        CP_WAIT2();
        __syncthreads();

        const uint32_t st = sbase + (t & 3) * 16384;
        #pragma unroll
        for (int ks = 0; ks < 2; ++ks) {
            uint32_t a[4][4];
            #pragma unroll
            for (int mf = 0; mf < 4; ++mf)
                ldsm_x4(a[mf][0], a[mf][1], a[mf][2], a[mf][3], st + aoff[ks][mf]);
            uint32_t b[2][4];
            #pragma unroll
            for (int np = 0; np < 2; ++np)
                ldsm_x4(b[np][0], b[np][1], b[np][2], b[np][3], st + boff[ks][np]);
            #pragma unroll
            for (int mf = 0; mf < 4; ++mf)
                #pragma unroll
                for (int nf = 0; nf < 4; ++nf) {
                    const int np = nf >> 1, hl = nf & 1;
                    mma_bf16(acc[mf][nf], a[mf][0], a[mf][1], a[mf][2], a[mf][3],
                             b[np][0 + hl], b[np][2 + hl]);
                }
        }

        if (t + 3 < T) load_stage(t + 3, (t + 3) & 3);
        CP_COMMIT();
    }

    const int g  = lane >> 2;
    const int cl = (lane & 3) * 2;
    #pragma unroll
    for (int mf = 0; mf < 4; ++mf) {
        const int mrow = by * 128 + warp_m * 64 + mf * 16 + g;
        #pragma unroll
        for (int nf = 0; nf < 4; ++nf) {
            const int col = bx * 128 + warp_n * 32 + nf * 8 + cl;
            const float b0 = bias[col], b1 = bias[col + 1];
            float v[4] = { acc[mf][nf][0] + b0, acc[mf][nf][1] + b1,
                           acc[mf][nf][2] + b0, acc[mf][nf][3] + b1 };
            if constexpr (MODE == 0) {
                *(float2*)(C + (size_t)mrow * N + col)       = make_float2(v[0], v[1]);
                *(float2*)(C + (size_t)(mrow + 8) * N + col) = make_float2(v[2], v[3]);
            } else {
                const int which = col >> 10;           // 0=q 1=k 2=v
                const int h = (col >> 6) & 15;
                const int d = col & 63;
                const int bb = mrow >> 11;
                const int n0 = mrow & 2047;
                if (which == 0) { v[0]*=QSC; v[1]*=QSC; v[2]*=QSC; v[3]*=QSC; }
                #pragma unroll
                for (int rr = 0; rr < 2; ++rr) {
                    const int n = n0 + rr * 8;
                    __nv_bfloat16 h0,l0,h1,l1;
                    split_hl(v[rr*2+0], h0, l0);
                    split_hl(v[rr*2+1], h1, l1);
                    if (which < 2) {
                        const size_t base = (size_t)(bb*16 + h) * (SEQ*HDIM)
                                          + (size_t)n * HDIM + d;
                        __nv_bfloat16* PH = which ? kh : qh;
                        __nv_bfloat16* PL = which ? kl : ql;
                        *(uint32_t*)(PH + base) = pack2bf(h0, h1);
                        *(uint32_t*)(PL + base) = pack2bf(l0, l1);
                    } else {
                        const size_t base = (size_t)(bb*16 + h) * (SEQ*HDIM)
                                          + (size_t)d * SEQ + n;
                        vh[base]       = h0;  vh[base + SEQ] = h1;
                        vl[base]       = l0;  vl[base + SEQ] = l1;
                    }
                }
            }
        }
    }
}

// ---------------------------------------------------------------------------
// k2: flash attention on HMMA, 128 thr (4 warps 2x2), double-buffered K/V,
// operand-reuse ordering: per unit u, load Qhi/Qlo/Khi/Klo fragments once
// and issue all 3 split products. ldsm/iter 96 -> 64. No register caching.
// smem: Qa 16K | Ka[2] 32K | Va[2] 32K | Pa 16K | stats 1.5K = 99840 B.
// ---------------------------------------------------------------------------
#define FLASH_SMEM (98304 + 1536)

__global__ void __launch_bounds__(128)
flash_mma_kernel(const __nv_bfloat16* __restrict__ qhi, const __nv_bfloat16* __restrict__ qlo,
                 const __nv_bfloat16* __restrict__ khi, const __nv_bfloat16* __restrict__ klo,
                 const __nv_bfloat16* __restrict__ vhiT, const __nv_bfloat16* __restrict__ vloT,
                 __nv_bfloat16* __restrict__ atta)
{
    extern __shared__ __align__(1024) uint8_t fsm[];
    uint8_t* Pa_c = fsm + 81920;
    float* pmax = (float*)(fsm + 98304);     // [2][64]
    float* psum = pmax + 128;                // [2][64]
    float* m_s  = psum + 128;                // [64]
    float* l_s  = m_s + 64;                  // [64]

    const uint32_t sbase = smem_u32(fsm);
    const uint32_t qa_u  = sbase;
    const uint32_t ka_u0 = sbase + 16384;    // + buf*16384
    const uint32_t va_u0 = sbase + 49152;    // + buf*16384
    const uint32_t pa_u  = sbase + 81920;

    const int tid  = threadIdx.x;
    const int wid  = tid >> 5;
    const int lane = tid & 31;
    const int warpM = wid >> 1;
    const int warpN = wid & 1;
    const int g  = lane >> 2;
    const int qd = lane & 3;
    const int rlo = lane & 15, hi = lane >> 4;

    const int qt = blockIdx.x, bh = blockIdx.y;
    const int q0 = qt * 64;

    // Q load
    {
        const size_t qbase = ((size_t)bh * SEQ + q0) * HDIM;
        for (int i = tid; i < 1024; i += 128) {
            const int r = i >> 4, c = i & 15;
            CP_ASYNC16(qa_u + foff(r, c),
                       (c < 8 ? qhi : qlo) + qbase + r * HDIM + (c & 7) * 8);
        }
        CP_COMMIT();
    }

    auto load_kv = [&](int kt, int buf) {
        const size_t kbase = ((size_t)bh * SEQ + kt * 64) * HDIM;
        const uint32_t ka = ka_u0 + buf * 16384, va = va_u0 + buf * 16384;
        for (int i = tid; i < 1024; i += 128) {
            const int r = i >> 4, c = i & 15;
            CP_ASYNC16(ka + foff(r, c),
                       (c < 8 ? khi : klo) + kbase + r * HDIM + (c & 7) * 8);
            CP_ASYNC16(va + foff(r, c),
                       (c < 8 ? vhiT : vloT) + (size_t)(bh * HDIM + r) * SEQ
                                             + kt * 64 + (c & 7) * 8);
        }
    };

    load_kv(0, 0); CP_COMMIT();
    if (tid < 64) { m_s[tid] = -1e30f; l_s[tid] = 0.f; }

    float oacc[2][4][4] = {};

    for (int kt = 0; kt < 32; ++kt) {
        const int buf = kt & 1;
        __syncthreads();              // (a) prior iter fully done
        if (kt + 1 < 32) load_kv(kt + 1, buf ^ 1);
        CP_COMMIT();
        CP_WAIT1();                   // KV(kt) landed
        __syncthreads();              // (b) everyone's KV(kt) visible

        const uint32_t ka_u = ka_u0 + buf * 16384;
        const uint32_t va_u = va_u0 + buf * 16384;

        // ---- S = Qhi.Khi + Qlo.Khi + Qhi.Klo, per-unit fragment reuse ----
        float sacc[2][4][4] = {};
        #pragma unroll
        for (int u = 0; u < 4; ++u) {
            uint32_t ah[2][4], al[2][4], bh_[2][4], bl[2][4];
            #pragma unroll
            for (int m = 0; m < 2; ++m) {
                ldsm_x4(ah[m][0], ah[m][1], ah[m][2], ah[m][3],
                        qa_u + foff(warpM*32 + m*16 + rlo, 2*u + hi));
                ldsm_x4(al[m][0], al[m][1], al[m][2], al[m][3],
                        qa_u + foff(warpM*32 + m*16 + rlo, 2*(u+4) + hi));
            }
            #pragma unroll
            for (int np = 0; np < 2; ++np) {
                ldsm_x4(bh_[np][0], bh_[np][1], bh_[np][2], bh_[np][3],
                        ka_u + foff(warpN*32 + np*16 + rlo, 2*u + hi));
                ldsm_x4(bl[np][0], bl[np][1], bl[np][2], bl[np][3],
                        ka_u + foff(warpN*32 + np*16 + rlo, 2*(u+4) + hi));
            }
            #pragma unroll
            for (int m = 0; m < 2; ++m)
                #pragma unroll
                for (int nf = 0; nf < 4; ++nf) {
                    const int np = nf >> 1, hl = nf & 1;
                    mma_bf16(sacc[m][nf], ah[m][0], ah[m][1], ah[m][2], ah[m][3],
                             bh_[np][0 + hl], bh_[np][2 + hl]);
                    mma_bf16(sacc[m][nf], al[m][0], al[m][1], al[m][2], al[m][3],
                             bh_[np][0 + hl], bh_[np][2 + hl]);
                    mma_bf16(sacc[m][nf], ah[m][0], ah[m][1], ah[m][2], ah[m][3],
                             bl[np][0 + hl], bl[np][2 + hl]);
                }
        }

        // ---- softmax ----
        float tmax[2][2];
        #pragma unroll
        for (int m = 0; m < 2; ++m)
            #pragma unroll
            for (int gg = 0; gg < 2; ++gg) {
                float mx = -1e30f;
                #pragma unroll
                for (int nf = 0; nf < 4; ++nf)
                    mx = fmaxf(mx, fmaxf(sacc[m][nf][gg*2], sacc[m][nf][gg*2+1]));
                tmax[m][gg] = mx;
            }
        #pragma unroll
        for (int o = 1; o <= 2; o <<= 1)
            #pragma unroll
            for (int m = 0; m < 2; ++m)
                #pragma unroll
                for (int gg = 0; gg < 2; ++gg)
                    tmax[m][gg] = fmaxf(tmax[m][gg],
                                        __shfl_xor_sync(0xffffffffu, tmax[m][gg], o));
        if (qd == 0)
            #pragma unroll
            for (int m = 0; m < 2; ++m)
                #pragma unroll
                for (int gg = 0; gg < 2; ++gg)
                    pmax[warpN*64 + warpM*32 + m*16 + g + gg*8] = tmax[m][gg];
        __syncthreads();   // b1

        float corr[2][2], tsum[2][2];
        #pragma unroll
        for (int m = 0; m < 2; ++m)
            #pragma unroll
            for (int gg = 0; gg < 2; ++gg) {
                const int r = warpM*32 + m*16 + g + gg*8;
                const float mx = fmaxf(pmax[r], pmax[64 + r]);
                const float mo = m_s[r];
                const float mn = fmaxf(mo, mx);
                corr[m][gg] = exp2f(mo - mn);
                float sum = 0.f;
                #pragma unroll
                for (int nf = 0; nf < 4; ++nf) {
                    const float p0 = exp2f(sacc[m][nf][gg*2]   - mn);
                    const float p1 = exp2f(sacc[m][nf][gg*2+1] - mn);
                    sum += p0 + p1;
                    __nv_bfloat16 h0,l0,h1,l1;
                    split_hl(p0, h0, l0);
                    split_hl(p1, h1, l1);
                    const int chunk = warpN*4 + nf;
                    *(uint32_t*)(Pa_c + foff(r, chunk)     + qd*4) = pack2bf(h0, h1);
                    *(uint32_t*)(Pa_c + foff(r, chunk + 8) + qd*4) = pack2bf(l0, l1);
                }
                tsum[m][gg] = sum;
            }
        #pragma unroll
        for (int o = 1; o <= 2; o <<= 1)
            #pragma unroll
            for (int m = 0; m < 2; ++m)
                #pragma unroll
                for (int gg = 0; gg < 2; ++gg)
                    tsum[m][gg] += __shfl_xor_sync(0xffffffffu, tsum[m][gg], o);
        if (qd == 0)
            #pragma unroll
            for (int m = 0; m < 2; ++m)
                #pragma unroll
                for (int gg = 0; gg < 2; ++gg)
                    psum[warpN*64 + warpM*32 + m*16 + g + gg*8] = tsum[m][gg];
        #pragma unroll
        for (int m = 0; m < 2; ++m)
            #pragma unroll
            for (int nf = 0; nf < 4; ++nf) {
                oacc[m][nf][0] *= corr[m][0];
                oacc[m][nf][1] *= corr[m][0];
                oacc[m][nf][2] *= corr[m][1];
                oacc[m][nf][3] *= corr[m][1];
            }
        __syncthreads();   // b2: Pa + psum visible

        if (tid < 64) {
            const float mo = m_s[tid];
            const float mx = fmaxf(pmax[tid], pmax[64 + tid]);
            const float mn = fmaxf(mo, mx);
            const float cr = exp2f(mo - mn);
            l_s[tid] = l_s[tid] * cr + psum[tid] + psum[64 + tid];
            m_s[tid] = mn;
        }

        // ---- O += Phi.Vhi + Plo.Vhi + Phi.Vlo, per-unit fragment reuse ----
        #pragma unroll
        for (int u = 0; u < 4; ++u) {
            uint32_t ah[2][4], al[2][4], bh_[2][4], bl[2][4];
            #pragma unroll
            for (int m = 0; m < 2; ++m) {
                ldsm_x4(ah[m][0], ah[m][1], ah[m][2], ah[m][3],
                        pa_u + foff(warpM*32 + m*16 + rlo, 2*u + hi));
                ldsm_x4(al[m][0], al[m][1], al[m][2], al[m][3],
                        pa_u + foff(warpM*32 + m*16 + rlo, 2*(u+4) + hi));
            }
            #pragma unroll
            for (int np = 0; np < 2; ++np) {
                ldsm_x4(bh_[np][0], bh_[np][1], bh_[np][2], bh_[np][3],
                        va_u + foff(warpN*32 + np*16 + rlo, 2*u + hi));
                ldsm_x4(bl[np][0], bl[np][1], bl[np][2], bl[np][3],
                        va_u + foff(warpN*32 + np*16 + rlo, 2*(u+4) + hi));
            }
            #pragma unroll
            for (int m = 0; m < 2; ++m)
                #pragma unroll
                for (int nf = 0; nf < 4; ++nf) {
                    const int np = nf >> 1, hl = nf & 1;
                    mma_bf16(oacc[m][nf], ah[m][0], ah[m][1], ah[m][2], ah[m][3],
                             bh_[np][0 + hl], bh_[np][2 + hl]);
                    mma_bf16(oacc[m][nf], al[m][0], al[m][1], al[m][2], al[m][3],
                             bh_[np][0 + hl], bh_[np][2 + hl]);
                    mma_bf16(oacc[m][nf], ah[m][0], ah[m][1], ah[m][2], ah[m][3],
                             bl[np][0 + hl], bl[np][2 + hl]);
                }
        }
    }
    __syncthreads();

    const int b_ = bh >> 4, h = bh & 15;
    float inv[2][2];
    #pragma unroll
    for (int m = 0; m < 2; ++m)
        #pragma unroll
        for (int gg = 0; gg < 2; ++gg)
            inv[m][gg] = 1.f / l_s[warpM*32 + m*16 + g + gg*8];

    #pragma unroll
    for (int m = 0; m < 2; ++m)
        #pragma unroll
        for (int nf = 0; nf < 4; ++nf) {
            const int colL = warpN*32 + nf*8 + qd*2;
            #pragma unroll
            for (int gg = 0; gg < 2; ++gg) {
                const int r = warpM*32 + m*16 + g + gg*8;
                const float v0 = oacc[m][nf][gg*2]   * inv[m][gg];
                const float v1 = oacc[m][nf][gg*2+1] * inv[m][gg];
                __nv_bfloat16 h0,l0,h1,l1;
                split_hl(v0, h0, l0);
                split_hl(v1, h1, l1);
                const size_t ro = (size_t)(b_*SEQ + q0 + r) * KAUG + h*64 + colL;
                *(uint32_t*)(atta + ro)            = pack2bf(h0, h1);
                *(uint32_t*)(atta + ro + EMBED)    = pack2bf(l0, l1);
                *(uint32_t*)(atta + ro + 2*EMBED)  = pack2bf(h0, h1);
            }
        }
}

// ---------------------------------------------------------------------------
// Launch
// ---------------------------------------------------------------------------
extern "C" void kernel_launch(void* const* d_in, const int* in_sizes, int n_in,
                              void* d_out, int out_size)
{
    const float* x      = (const float*)d_in[0];
    const float* w_qkv  = (const float*)d_in[1];
    const float* b_qkv  = (const float*)d_in[2];
    const float* w_proj = (const float*)d_in[3];
    const float* b_proj = (const float*)d_in[4];
    float* out = (float*)d_out;

    __nv_bfloat16 *xa, *atta, *wqkvT, *wprojT, *qh, *ql, *kh, *kl, *vh, *vl;
    cudaGetSymbolAddress((void**)&xa,     g_xa);
    cudaGetSymbolAddress((void**)&atta,   g_atta);
    cudaGetSymbolAddress((void**)&wqkvT,  g_wqkvT);
    cudaGetSymbolAddress((void**)&wprojT, g_wprojT);
    cudaGetSymbolAddress((void**)&qh,     g_qhi);
    cudaGetSymbolAddress((void**)&ql,     g_qlo);
    cudaGetSymbolAddress((void**)&kh,     g_khi);
    cudaGetSymbolAddress((void**)&kl,     g_klo);
    cudaGetSymbolAddress((void**)&vh,     g_vhiT);
    cudaGetSymbolAddress((void**)&vl,     g_vloT);

    cudaFuncSetAttribute(mma_gemm_kernel<1>,
                         cudaFuncAttributeMaxDynamicSharedMemorySize, GEMM_SMEM);
    cudaFuncSetAttribute(mma_gemm_kernel<0>,
                         cudaFuncAttributeMaxDynamicSharedMemorySize, GEMM_SMEM);
    cudaFuncSetAttribute(flash_mma_kernel,
                         cudaFuncAttributeMaxDynamicSharedMemorySize, FLASH_SMEM);

    split_x_kernel<<<MROWS, 256>>>(x, xa);
    transpose_split_kernel<<<dim3(QKV_N/32, EMBED/32), dim3(32,8)>>>(w_qkv, wqkvT, EMBED, QKV_N);
    transpose_split_kernel<<<dim3(EMBED/32, EMBED/32), dim3(32,8)>>>(w_proj, wprojT, EMBED, EMBED);

    mma_gemm_kernel<1><<<dim3(QKV_N/128, MROWS/128), 256, GEMM_SMEM>>>(
        xa, wqkvT, b_qkv, nullptr, qh, ql, kh, kl, vh, vl, MROWS, QKV_N, KAUG);

    flash_mma_kernel<<<dim3(SEQ/64, NBH), 128, FLASH_SMEM>>>(qh, ql, kh, kl, vh, vl, atta);

    mma_gemm_kernel<0><<<dim3(EMBED/128, MROWS/128), 256, GEMM_SMEM>>>(
        atta, wprojT, b_proj, out, nullptr, nullptr, nullptr, nullptr, nullptr, nullptr,
        MROWS, EMBED, KAUG);
}

// round 11
// speedup vs baseline: 1.0913x; 1.0167x over previous
#include <cuda_runtime.h>
#include <cuda_bf16.h>
#include <cstdint>

// ===========================================================================
// MultiHeadSelfAttention, sm_100 (mma.sync HMMA path everywhere).
//   s1: split x -> xa bf16 [8192 x 3072] ([hi|lo|hi])
//   s2/s3: transpose+split weights -> [N x 3K] bf16 ([hi|hi|lo])
//   k1: qkv GEMM (BK=32, 4-stage cp.async) -> split planes. Q pre-scaled.
//   k2: flash attention, 128 thr, double-buffered K/V, register-resident P
//       (S C-frags repacked as PV A-frags, no smem P tile), warpN splits keys
//       in PV with end-of-kernel O partial reduction -> augmented atta.
//   k3: out = atta @ wprojT^T + b_proj.
// ===========================================================================

#define EMBED   1024
#define HEADS   16
#define HDIM    64
#define BATCH   4
#define SEQ     2048
#define MROWS   (BATCH * SEQ)     // 8192
#define QKV_N   (3 * EMBED)       // 3072
#define KAUG    (3 * EMBED)       // 3072
#define NBH     (BATCH * HEADS)   // 64
#define QSC     (0.125f * 1.44269504f)

__device__ __nv_bfloat16  g_xa[(size_t)MROWS * KAUG];       // 48 MB
__device__ __nv_bfloat16  g_atta[(size_t)MROWS * KAUG];     // 48 MB
__device__ __nv_bfloat16  g_wqkvT[(size_t)QKV_N * KAUG];    // 18 MB
__device__ __nv_bfloat16  g_wprojT[(size_t)EMBED * KAUG];   //  6 MB
__device__ __nv_bfloat16  g_qhi[(size_t)NBH * SEQ * HDIM];
__device__ __nv_bfloat16  g_qlo[(size_t)NBH * SEQ * HDIM];
__device__ __nv_bfloat16  g_khi[(size_t)NBH * SEQ * HDIM];
__device__ __nv_bfloat16  g_klo[(size_t)NBH * SEQ * HDIM];
__device__ __nv_bfloat16  g_vhiT[(size_t)NBH * HDIM * SEQ];
__device__ __nv_bfloat16  g_vloT[(size_t)NBH * HDIM * SEQ];

// ---------------------------------------------------------------------------
// helpers
// ---------------------------------------------------------------------------
__device__ __forceinline__ uint32_t smem_u32(const void* p) {
    uint32_t a;
    asm("{ .reg .u64 t; cvta.to.shared.u64 t, %1; cvt.u32.u64 %0, t; }"
        : "=r"(a) : "l"(p));
    return a;
}
__device__ __forceinline__ void ldsm_x4(uint32_t& r0, uint32_t& r1,
                                        uint32_t& r2, uint32_t& r3, uint32_t addr) {
    asm volatile("ldmatrix.sync.aligned.m8n8.x4.shared.b16 {%0,%1,%2,%3}, [%4];"
                 : "=r"(r0), "=r"(r1), "=r"(r2), "=r"(r3) : "r"(addr));
}
__device__ __forceinline__ void mma_bf16(float* c, uint32_t a0, uint32_t a1,
                                         uint32_t a2, uint32_t a3,
                                         uint32_t b0, uint32_t b1) {
    asm volatile(
        "mma.sync.aligned.m16n8k16.row.col.f32.bf16.bf16.f32 "
        "{%0,%1,%2,%3}, {%4,%5,%6,%7}, {%8,%9}, {%0,%1,%2,%3};"
        : "+f"(c[0]), "+f"(c[1]), "+f"(c[2]), "+f"(c[3])
        : "r"(a0), "r"(a1), "r"(a2), "r"(a3), "r"(b0), "r"(b1));
}
#define CP_ASYNC16(smem, gptr) \
    asm volatile("cp.async.cg.shared.global [%0], [%1], 16;" :: "r"(smem), "l"(gptr))
#define CP_COMMIT() asm volatile("cp.async.commit_group;" ::: "memory")
#define CP_WAIT1()  asm volatile("cp.async.wait_group 1;" ::: "memory")
#define CP_WAIT2()  asm volatile("cp.async.wait_group 2;" ::: "memory")
#define BAR_GROUP(id) \
    asm volatile("bar.sync %0, 64;" :: "r"(id) : "memory")

// GEMM tile (64B rows): chunk' = chunk ^ ((row>>1)&3)
__device__ __forceinline__ uint32_t tile_off(int r, int c) {
    return (uint32_t)(r * 64 + ((c ^ ((r >> 1) & 3)) << 4));
}
// Flash tile (256B rows, 16 chunks): chunk' = chunk ^ (row & 7)
__device__ __forceinline__ uint32_t foff(int r, int c) {
    return (uint32_t)(r * 256 + ((c ^ (r & 7)) << 4));
}

__device__ __forceinline__ void split_hl(float v, __nv_bfloat16& hi, __nv_bfloat16& lo) {
    hi = __float2bfloat16_rn(v);
    lo = __float2bfloat16_rn(v - __bfloat162float(hi));
}
__device__ __forceinline__ uint32_t pack2bf(__nv_bfloat16 a, __nv_bfloat16 b) {
    __nv_bfloat162 p(a, b);
    return *reinterpret_cast<uint32_t*>(&p);
}
// pack high halves of two fp32 -> bf16x2 (truncation split)
__device__ __forceinline__ uint32_t prmt_hi(float a, float b) {
    return __byte_perm(__float_as_uint(a), __float_as_uint(b), 0x7632);
}
__device__ __forceinline__ float trunc_res(float v) {
    return v - __uint_as_float(__float_as_uint(v) & 0xFFFF0000u);
}

// ---------------------------------------------------------------------------
// s1: split x -> xa [hi | lo | hi]
// ---------------------------------------------------------------------------
__global__ void __launch_bounds__(256)
split_x_kernel(const float* __restrict__ x, __nv_bfloat16* __restrict__ xa)
{
    const int row = blockIdx.x;
    const int c = threadIdx.x * 4;
    float4 v = *(const float4*)(x + (size_t)row * EMBED + c);
    __nv_bfloat16 h0,h1,h2,h3,l0,l1,l2,l3;
    split_hl(v.x, h0, l0); split_hl(v.y, h1, l1);
    split_hl(v.z, h2, l2); split_hl(v.w, h3, l3);
    const size_t o = (size_t)row * KAUG + c;
    uint2 uh; uh.x = pack2bf(h0,h1); uh.y = pack2bf(h2,h3);
    uint2 ul; ul.x = pack2bf(l0,l1); ul.y = pack2bf(l2,l3);
    *(uint2*)(xa + o)           = uh;
    *(uint2*)(xa + o + EMBED)   = ul;
    *(uint2*)(xa + o + 2*EMBED) = uh;
}

// ---------------------------------------------------------------------------
// s2/s3: W [K x N] fp32 -> Bp [N x 3K] bf16 ([hi | hi | lo])
// ---------------------------------------------------------------------------
__global__ void __launch_bounds__(256)
transpose_split_kernel(const float* __restrict__ W, __nv_bfloat16* __restrict__ Bp,
                       int K, int N)
{
    __shared__ float t[32][33];
    const int n0 = blockIdx.x * 32, k0 = blockIdx.y * 32;
    const int tx = threadIdx.x, ty = threadIdx.y;
    #pragma unroll
    for (int i = 0; i < 4; ++i)
        t[ty + 8*i][tx] = W[(size_t)(k0 + ty + 8*i) * N + n0 + tx];
    __syncthreads();
    #pragma unroll
    for (int i = 0; i < 4; ++i) {
        const int n = ty + 8*i;
        float v = t[tx][n];
        __nv_bfloat16 hi, lo;
        split_hl(v, hi, lo);
        const size_t ro = (size_t)(n0 + n) * (3*K);
        Bp[ro + k0 + tx]       = hi;
        Bp[ro + K + k0 + tx]   = hi;
        Bp[ro + 2*K + k0 + tx] = lo;
    }
}

// ---------------------------------------------------------------------------
// HMMA GEMM (round-6 best): 128x128x32 tile, 8 warps (2x4), 4-stage cp.async.
// dyn smem = 4 x 16KB = 64KB.
// MODE 0: C = A@B^T + bias.  MODE 1: qkv epilogue -> split planes.
// ---------------------------------------------------------------------------
#define GEMM_SMEM 65536

template<int MODE>
__global__ void __launch_bounds__(256)
mma_gemm_kernel(const __nv_bfloat16* __restrict__ A, const __nv_bfloat16* __restrict__ B,
                const float* __restrict__ bias, float* __restrict__ C,
                __nv_bfloat16* __restrict__ qh, __nv_bfloat16* __restrict__ ql,
                __nv_bfloat16* __restrict__ kh, __nv_bfloat16* __restrict__ kl,
                __nv_bfloat16* __restrict__ vh, __nv_bfloat16* __restrict__ vl,
                int M, int N, int K)
{
    extern __shared__ __align__(1024) uint8_t dsm[];

    const int tid  = threadIdx.x;
    const int wid  = tid >> 5;
    const int lane = tid & 31;
    const int bx = blockIdx.x, by = blockIdx.y;
    const int warp_m = wid & 1;
    const int warp_n = wid >> 1;
    const uint32_t sbase = smem_u32(dsm);

    const size_t Ks = (size_t)K;
    const __nv_bfloat16* Ab = A + (size_t)(by * 128) * Ks;
    const __nv_bfloat16* Bb = B + (size_t)(bx * 128) * Ks;

    const int lr0 = tid >> 2,         lc0 = tid & 3;
    const int lr1 = (tid + 256) >> 2, lc1 = (tid + 256) & 3;
    const __nv_bfloat16* Ag0 = Ab + (size_t)lr0 * Ks + lc0 * 8;
    const __nv_bfloat16* Ag1 = Ab + (size_t)lr1 * Ks + lc1 * 8;
    const __nv_bfloat16* Bg0 = Bb + (size_t)lr0 * Ks + lc0 * 8;
    const __nv_bfloat16* Bg1 = Bb + (size_t)lr1 * Ks + lc1 * 8;
    const uint32_t sA0 = tile_off(lr0, lc0), sA1 = tile_off(lr1, lc1);

    auto load_stage = [&](int kt, int st) {
        const int k0 = kt * 32;
        const uint32_t s = sbase + st * 16384;
        CP_ASYNC16(s + sA0,        Ag0 + k0);
        CP_ASYNC16(s + sA1,        Ag1 + k0);
        CP_ASYNC16(s + 8192 + sA0, Bg0 + k0);
        CP_ASYNC16(s + 8192 + sA1, Bg1 + k0);
    };

    uint32_t aoff[2][4], boff[2][2];
    #pragma unroll
    for (int ks = 0; ks < 2; ++ks) {
        #pragma unroll
        for (int mf = 0; mf < 4; ++mf)
            aoff[ks][mf] = tile_off(warp_m * 64 + mf * 16 + (lane & 15),
                                    ks * 2 + (lane >> 4));
        #pragma unroll
        for (int np = 0; np < 2; ++np)
            boff[ks][np] = 8192 + tile_off(warp_n * 32 + np * 16 + (lane & 15),
                                           ks * 2 + (lane >> 4));
    }

    float acc[4][4][4] = {};
    const int T = K >> 5;      // 96

    load_stage(0, 0); CP_COMMIT();
    load_stage(1, 1); CP_COMMIT();
    load_stage(2, 2); CP_COMMIT();

    for (int t = 0; t < T; ++t) {
        CP_WAIT2();
        __syncthreads();

        const uint32_t st = sbase + (t & 3) * 16384;
        #pragma unroll
        for (int ks = 0; ks < 2; ++ks) {
            uint32_t a[4][4];
            #pragma unroll
            for (int mf = 0; mf < 4; ++mf)
                ldsm_x4(a[mf][0], a[mf][1], a[mf][2], a[mf][3], st + aoff[ks][mf]);
            uint32_t b[2][4];
            #pragma unroll
            for (int np = 0; np < 2; ++np)
                ldsm_x4(b[np][0], b[np][1], b[np][2], b[np][3], st + boff[ks][np]);
            #pragma unroll
            for (int mf = 0; mf < 4; ++mf)
                #pragma unroll
                for (int nf = 0; nf < 4; ++nf) {
                    const int np = nf >> 1, hl = nf & 1;
                    mma_bf16(acc[mf][nf], a[mf][0], a[mf][1], a[mf][2], a[mf][3],
                             b[np][0 + hl], b[np][2 + hl]);
                }
        }

        if (t + 3 < T) load_stage(t + 3, (t + 3) & 3);
        CP_COMMIT();
    }

    const int g  = lane >> 2;
    const int cl = (lane & 3) * 2;
    #pragma unroll
    for (int mf = 0; mf < 4; ++mf) {
        const int mrow = by * 128 + warp_m * 64 + mf * 16 + g;
        #pragma unroll
        for (int nf = 0; nf < 4; ++nf) {
            const int col = bx * 128 + warp_n * 32 + nf * 8 + cl;
            const float b0 = bias[col], b1 = bias[col + 1];
            float v[4] = { acc[mf][nf][0] + b0, acc[mf][nf][1] + b1,
                           acc[mf][nf][2] + b0, acc[mf][nf][3] + b1 };
            if constexpr (MODE == 0) {
                *(float2*)(C + (size_t)mrow * N + col)       = make_float2(v[0], v[1]);
                *(float2*)(C + (size_t)(mrow + 8) * N + col) = make_float2(v[2], v[3]);
            } else {
                const int which = col >> 10;           // 0=q 1=k 2=v
                const int h = (col >> 6) & 15;
                const int d = col & 63;
                const int bb = mrow >> 11;
                const int n0 = mrow & 2047;
                if (which == 0) { v[0]*=QSC; v[1]*=QSC; v[2]*=QSC; v[3]*=QSC; }
                #pragma unroll
                for (int rr = 0; rr < 2; ++rr) {
                    const int n = n0 + rr * 8;
                    __nv_bfloat16 h0,l0,h1,l1;
                    split_hl(v[rr*2+0], h0, l0);
                    split_hl(v[rr*2+1], h1, l1);
                    if (which < 2) {
                        const size_t base = (size_t)(bb*16 + h) * (SEQ*HDIM)
                                          + (size_t)n * HDIM + d;
                        __nv_bfloat16* PH = which ? kh : qh;
                        __nv_bfloat16* PL = which ? kl : ql;
                        *(uint32_t*)(PH + base) = pack2bf(h0, h1);
                        *(uint32_t*)(PL + base) = pack2bf(l0, l1);
                    } else {
                        const size_t base = (size_t)(bb*16 + h) * (SEQ*HDIM)
                                          + (size_t)d * SEQ + n;
                        vh[base]       = h0;  vh[base + SEQ] = h1;
                        vl[base]       = l0;  vl[base + SEQ] = l1;
                    }
                }
            }
        }
    }
}

// ---------------------------------------------------------------------------
// k2: flash attention, 128 thr (4 warps 2x2), double-buffered K/V.
// S phase: warpN splits keys (as before). PV phase: P stays in REGISTERS
// (C-frag -> A-frag repack via PRMT truncation split); warpN keeps its key
// subset, accumulates O over ALL 64 d-cols; warpN pair reduced in epilogue
// through the 16KB freed by deleting the Pa tile.
// smem: Qa 16K | Ka[2] 32K | Va[2] 32K | Obuf 16K | stats 1.5K = 99840 B.
// ---------------------------------------------------------------------------
#define FLASH_SMEM (98304 + 1536)

__global__ void __launch_bounds__(128)
flash_mma_kernel(const __nv_bfloat16* __restrict__ qhi, const __nv_bfloat16* __restrict__ qlo,
                 const __nv_bfloat16* __restrict__ khi, const __nv_bfloat16* __restrict__ klo,
                 const __nv_bfloat16* __restrict__ vhiT, const __nv_bfloat16* __restrict__ vloT,
                 __nv_bfloat16* __restrict__ atta)
{
    extern __shared__ __align__(1024) uint8_t fsm[];
    float* Obuf = (float*)(fsm + 81920);     // [2][32][64] fp32
    float* pmax = (float*)(fsm + 98304);     // [2][64]
    float* psum = pmax + 128;                // [2][64]
    float* m_s  = psum + 128;                // [64]
    float* l_s  = m_s + 64;                  // [64]

    const uint32_t sbase = smem_u32(fsm);
    const uint32_t qa_u  = sbase;
    const uint32_t ka_u0 = sbase + 16384;    // + buf*16384
    const uint32_t va_u0 = sbase + 49152;    // + buf*16384

    const int tid  = threadIdx.x;
    const int wid  = tid >> 5;
    const int lane = tid & 31;
    const int warpM = wid >> 1;
    const int warpN = wid & 1;
    const int g  = lane >> 2;
    const int qd = lane & 3;
    const int rlo = lane & 15, hi = lane >> 4;

    const int qt = blockIdx.x, bh = blockIdx.y;
    const int q0 = qt * 64;

    // Q load
    {
        const size_t qbase = ((size_t)bh * SEQ + q0) * HDIM;
        for (int i = tid; i < 1024; i += 128) {
            const int r = i >> 4, c = i & 15;
            CP_ASYNC16(qa_u + foff(r, c),
                       (c < 8 ? qhi : qlo) + qbase + r * HDIM + (c & 7) * 8);
        }
        CP_COMMIT();
    }

    auto load_kv = [&](int kt, int buf) {
        const size_t kbase = ((size_t)bh * SEQ + kt * 64) * HDIM;
        const uint32_t ka = ka_u0 + buf * 16384, va = va_u0 + buf * 16384;
        for (int i = tid; i < 1024; i += 128) {
            const int r = i >> 4, c = i & 15;
            CP_ASYNC16(ka + foff(r, c),
                       (c < 8 ? khi : klo) + kbase + r * HDIM + (c & 7) * 8);
            CP_ASYNC16(va + foff(r, c),
                       (c < 8 ? vhiT : vloT) + (size_t)(bh * HDIM + r) * SEQ
                                             + kt * 64 + (c & 7) * 8);
        }
    };

    load_kv(0, 0); CP_COMMIT();
    if (tid < 64) { m_s[tid] = -1e30f; l_s[tid] = 0.f; }

    // stats updater (designated threads): rows of own warpM group
    auto update_stats = [&]() {
        #pragma unroll
        for (int m = 0; m < 2; ++m)
            #pragma unroll
            for (int gg = 0; gg < 2; ++gg) {
                const int r = warpM*32 + m*16 + g + gg*8;
                const float mx = fmaxf(pmax[r], pmax[64 + r]);
                const float mo = m_s[r];
                const float mn = fmaxf(mo, mx);
                l_s[r] = l_s[r] * exp2f(mo - mn) + psum[r] + psum[64 + r];
                m_s[r] = mn;
            }
    };

    float oacc[2][8][4] = {};   // [m][d-tile nf_o][reg]

    for (int kt = 0; kt < 32; ++kt) {
        const int buf = kt & 1;
        __syncthreads();              // (a) prior iter fully done
        if (kt > 0 && warpN == 0 && qd == 0) update_stats();   // prev-iter stats
        if (kt + 1 < 32) load_kv(kt + 1, buf ^ 1);
        CP_COMMIT();
        CP_WAIT1();                   // KV(kt) landed
        __syncthreads();              // (b) everyone's KV(kt) visible

        const uint32_t ka_u = ka_u0 + buf * 16384;
        const uint32_t va_u = va_u0 + buf * 16384;

        // ---- S = Qhi.Khi + Qlo.Khi + Qhi.Klo, per-unit fragment reuse ----
        float sacc[2][4][4] = {};
        #pragma unroll
        for (int u = 0; u < 4; ++u) {
            uint32_t ah[2][4], al[2][4], bh_[2][4], bl[2][4];
            #pragma unroll
            for (int m = 0; m < 2; ++m) {
                ldsm_x4(ah[m][0], ah[m][1], ah[m][2], ah[m][3],
                        qa_u + foff(warpM*32 + m*16 + rlo, 2*u + hi));
                ldsm_x4(al[m][0], al[m][1], al[m][2], al[m][3],
                        qa_u + foff(warpM*32 + m*16 + rlo, 2*(u+4) + hi));
            }
            #pragma unroll
            for (int np = 0; np < 2; ++np) {
                ldsm_x4(bh_[np][0], bh_[np][1], bh_[np][2], bh_[np][3],
                        ka_u + foff(warpN*32 + np*16 + rlo, 2*u + hi));
                ldsm_x4(bl[np][0], bl[np][1], bl[np][2], bl[np][3],
                        ka_u + foff(warpN*32 + np*16 + rlo, 2*(u+4) + hi));
            }
            #pragma unroll
            for (int m = 0; m < 2; ++m)
                #pragma unroll
                for (int nf = 0; nf < 4; ++nf) {
                    const int np = nf >> 1, hl = nf & 1;
                    mma_bf16(sacc[m][nf], ah[m][0], ah[m][1], ah[m][2], ah[m][3],
                             bh_[np][0 + hl], bh_[np][2 + hl]);
                    mma_bf16(sacc[m][nf], al[m][0], al[m][1], al[m][2], al[m][3],
                             bh_[np][0 + hl], bh_[np][2 + hl]);
                    mma_bf16(sacc[m][nf], ah[m][0], ah[m][1], ah[m][2], ah[m][3],
                             bl[np][0 + hl], bl[np][2 + hl]);
                }
        }

        // ---- row-max: quad shuffle + cross-warpN exchange (group barrier) ----
        float tmax[2][2];
        #pragma unroll
        for (int m = 0; m < 2; ++m)
            #pragma unroll
            for (int gg = 0; gg < 2; ++gg) {
                float mx = -1e30f;
                #pragma unroll
                for (int nf = 0; nf < 4; ++nf)
                    mx = fmaxf(mx, fmaxf(sacc[m][nf][gg*2], sacc[m][nf][gg*2+1]));
                tmax[m][gg] = mx;
            }
        #pragma unroll
        for (int o = 1; o <= 2; o <<= 1)
            #pragma unroll
            for (int m = 0; m < 2; ++m)
                #pragma unroll
                for (int gg = 0; gg < 2; ++gg)
                    tmax[m][gg] = fmaxf(tmax[m][gg],
                                        __shfl_xor_sync(0xffffffffu, tmax[m][gg], o));
        if (qd == 0)
            #pragma unroll
            for (int m = 0; m < 2; ++m)
                #pragma unroll
                for (int gg = 0; gg < 2; ++gg)
                    pmax[warpN*64 + warpM*32 + m*16 + g + gg*8] = tmax[m][gg];
        BAR_GROUP(warpM + 1);   // b1 (group-local)

        // ---- softmax: exp2 in regs, psum, rescale O, pack P into A-frags ----
        float pv_[2][4][4];
        float corr[2][2], tsum[2][2];
        #pragma unroll
        for (int m = 0; m < 2; ++m)
            #pragma unroll
            for (int gg = 0; gg < 2; ++gg) {
                const int r = warpM*32 + m*16 + g + gg*8;
                const float mx = fmaxf(pmax[r], pmax[64 + r]);
                const float mo = m_s[r];
                const float mn = fmaxf(mo, mx);
                corr[m][gg] = exp2f(mo - mn);
                float sum = 0.f;
                #pragma unroll
                for (int nf = 0; nf < 4; ++nf) {
                    const float p0 = exp2f(sacc[m][nf][gg*2]   - mn);
                    const float p1 = exp2f(sacc[m][nf][gg*2+1] - mn);
                    pv_[m][nf][gg*2]   = p0;
                    pv_[m][nf][gg*2+1] = p1;
                    sum += p0 + p1;
                }
                tsum[m][gg] = sum;
            }
        #pragma unroll
        for (int o = 1; o <= 2; o <<= 1)
            #pragma unroll
            for (int m = 0; m < 2; ++m)
                #pragma unroll
                for (int gg = 0; gg < 2; ++gg)
                    tsum[m][gg] += __shfl_xor_sync(0xffffffffu, tsum[m][gg], o);
        if (qd == 0)
            #pragma unroll
            for (int m = 0; m < 2; ++m)
                #pragma unroll
                for (int gg = 0; gg < 2; ++gg)
                    psum[warpN*64 + warpM*32 + m*16 + g + gg*8] = tsum[m][gg];
        #pragma unroll
        for (int m = 0; m < 2; ++m)
            #pragma unroll
            for (int nf = 0; nf < 8; ++nf) {
                oacc[m][nf][0] *= corr[m][0];
                oacc[m][nf][1] *= corr[m][0];
                oacc[m][nf][2] *= corr[m][1];
                oacc[m][nf][3] *= corr[m][1];
            }

        // pack P into PV A-fragments (hi = PRMT-trunc, lo = exact residue)
        uint32_t phi[2][2][4], plo[2][2][4];
        #pragma unroll
        for (int m = 0; m < 2; ++m)
            #pragma unroll
            for (int ku = 0; ku < 2; ++ku) {
                const int nf0 = 2*ku, nf1 = 2*ku + 1;
                phi[m][ku][0] = prmt_hi(pv_[m][nf0][0], pv_[m][nf0][1]);
                phi[m][ku][1] = prmt_hi(pv_[m][nf0][2], pv_[m][nf0][3]);
                phi[m][ku][2] = prmt_hi(pv_[m][nf1][0], pv_[m][nf1][1]);
                phi[m][ku][3] = prmt_hi(pv_[m][nf1][2], pv_[m][nf1][3]);
                plo[m][ku][0] = prmt_hi(trunc_res(pv_[m][nf0][0]), trunc_res(pv_[m][nf0][1]));
                plo[m][ku][1] = prmt_hi(trunc_res(pv_[m][nf0][2]), trunc_res(pv_[m][nf0][3]));
                plo[m][ku][2] = prmt_hi(trunc_res(pv_[m][nf1][0]), trunc_res(pv_[m][nf1][1]));
                plo[m][ku][3] = prmt_hi(trunc_res(pv_[m][nf1][2]), trunc_res(pv_[m][nf1][3]));
            }

        // ---- PV: O += Phi.Vhi + Plo.Vhi + Phi.Vlo over warp's 32 keys ----
        #pragma unroll
        for (int ku = 0; ku < 2; ++ku) {
            uint32_t vh_[4][4], vl_[4][4];
            #pragma unroll
            for (int j = 0; j < 4; ++j) {
                ldsm_x4(vh_[j][0], vh_[j][1], vh_[j][2], vh_[j][3],
                        va_u + foff(j*16 + rlo, 2*(warpN*2 + ku) + hi));
                ldsm_x4(vl_[j][0], vl_[j][1], vl_[j][2], vl_[j][3],
                        va_u + foff(j*16 + rlo, 2*(4 + warpN*2 + ku) + hi));
            }
            #pragma unroll
            for (int m = 0; m < 2; ++m)
                #pragma unroll
                for (int j = 0; j < 4; ++j)
                    #pragma unroll
                    for (int hl = 0; hl < 2; ++hl) {
                        const int nf_o = j*2 + hl;
                        mma_bf16(oacc[m][nf_o], phi[m][ku][0], phi[m][ku][1],
                                 phi[m][ku][2], phi[m][ku][3],
                                 vh_[j][hl], vh_[j][2 + hl]);
                        mma_bf16(oacc[m][nf_o], plo[m][ku][0], plo[m][ku][1],
                                 plo[m][ku][2], plo[m][ku][3],
                                 vh_[j][hl], vh_[j][2 + hl]);
                        mma_bf16(oacc[m][nf_o], phi[m][ku][0], phi[m][ku][1],
                                 phi[m][ku][2], phi[m][ku][3],
                                 vl_[j][hl], vl_[j][2 + hl]);
                    }
        }
    }

    // final stats update + cross-warpN O reduction + write
    __syncthreads();
    if (warpN == 0 && qd == 0) update_stats();
    if (warpN == 1) {
        #pragma unroll
        for (int m = 0; m < 2; ++m)
            #pragma unroll
            for (int nf = 0; nf < 8; ++nf)
                #pragma unroll
                for (int gg = 0; gg < 2; ++gg) {
                    float* dst = Obuf + warpM*2048 + (m*16 + g + gg*8)*64 + nf*8 + qd*2;
                    *(float2*)dst = make_float2(oacc[m][nf][gg*2], oacc[m][nf][gg*2+1]);
                }
    }
    __syncthreads();

    if (warpN == 0) {
        const int b_ = bh >> 4, h = bh & 15;
        float inv[2][2];
        #pragma unroll
        for (int m = 0; m < 2; ++m)
            #pragma unroll
            for (int gg = 0; gg < 2; ++gg)
                inv[m][gg] = 1.f / l_s[warpM*32 + m*16 + g + gg*8];

        #pragma unroll
        for (int m = 0; m < 2; ++m)
            #pragma unroll
            for (int nf = 0; nf < 8; ++nf)
                #pragma unroll
                for (int gg = 0; gg < 2; ++gg) {
                    const int r = warpM*32 + m*16 + g + gg*8;
                    const float* src = Obuf + warpM*2048 + (m*16 + g + gg*8)*64 + nf*8 + qd*2;
                    float2 o2 = *(const float2*)src;
                    const float v0 = (oacc[m][nf][gg*2]   + o2.x) * inv[m][gg];
                    const float v1 = (oacc[m][nf][gg*2+1] + o2.y) * inv[m][gg];
                    __nv_bfloat16 h0,l0,h1,l1;
                    split_hl(v0, h0, l0);
                    split_hl(v1, h1, l1);
                    const size_t ro = (size_t)(b_*SEQ + q0 + r) * KAUG + h*64 + nf*8 + qd*2;
                    *(uint32_t*)(atta + ro)            = pack2bf(h0, h1);
                    *(uint32_t*)(atta + ro + EMBED)    = pack2bf(l0, l1);
                    *(uint32_t*)(atta + ro + 2*EMBED)  = pack2bf(h0, h1);
                }
    }
}

// ---------------------------------------------------------------------------
// Launch
// ---------------------------------------------------------------------------
extern "C" void kernel_launch(void* const* d_in, const int* in_sizes, int n_in,
                              void* d_out, int out_size)
{
    const float* x      = (const float*)d_in[0];
    const float* w_qkv  = (const float*)d_in[1];
    const float* b_qkv  = (const float*)d_in[2];
    const float* w_proj = (const float*)d_in[3];
    const float* b_proj = (const float*)d_in[4];
    float* out = (float*)d_out;

    __nv_bfloat16 *xa, *atta, *wqkvT, *wprojT, *qh, *ql, *kh, *kl, *vh, *vl;
    cudaGetSymbolAddress((void**)&xa,     g_xa);
    cudaGetSymbolAddress((void**)&atta,   g_atta);
    cudaGetSymbolAddress((void**)&wqkvT,  g_wqkvT);
    cudaGetSymbolAddress((void**)&wprojT, g_wprojT);
    cudaGetSymbolAddress((void**)&qh,     g_qhi);
    cudaGetSymbolAddress((void**)&ql,     g_qlo);
    cudaGetSymbolAddress((void**)&kh,     g_khi);
    cudaGetSymbolAddress((void**)&kl,     g_klo);
    cudaGetSymbolAddress((void**)&vh,     g_vhiT);
    cudaGetSymbolAddress((void**)&vl,     g_vloT);

    cudaFuncSetAttribute(mma_gemm_kernel<1>,
                         cudaFuncAttributeMaxDynamicSharedMemorySize, GEMM_SMEM);
    cudaFuncSetAttribute(mma_gemm_kernel<0>,
                         cudaFuncAttributeMaxDynamicSharedMemorySize, GEMM_SMEM);
    cudaFuncSetAttribute(flash_mma_kernel,
                         cudaFuncAttributeMaxDynamicSharedMemorySize, FLASH_SMEM);

    split_x_kernel<<<MROWS, 256>>>(x, xa);
    transpose_split_kernel<<<dim3(QKV_N/32, EMBED/32), dim3(32,8)>>>(w_qkv, wqkvT, EMBED, QKV_N);
    transpose_split_kernel<<<dim3(EMBED/32, EMBED/32), dim3(32,8)>>>(w_proj, wprojT, EMBED, EMBED);

    mma_gemm_kernel<1><<<dim3(QKV_N/128, MROWS/128), 256, GEMM_SMEM>>>(
        xa, wqkvT, b_qkv, nullptr, qh, ql, kh, kl, vh, vl, MROWS, QKV_N, KAUG);

    flash_mma_kernel<<<dim3(SEQ/64, NBH), 128, FLASH_SMEM>>>(qh, ql, kh, kl, vh, vl, atta);

    mma_gemm_kernel<0><<<dim3(EMBED/128, MROWS/128), 256, GEMM_SMEM>>>(
        atta, wprojT, b_proj, out, nullptr, nullptr, nullptr, nullptr, nullptr, nullptr,
        MROWS, EMBED, KAUG);
}

// round 12
// speedup vs baseline: 1.1116x; 1.0186x over previous
#include <cuda_runtime.h>
#include <cuda_bf16.h>
#include <cstdint>

// ===========================================================================
// MultiHeadSelfAttention, sm_100 (mma.sync HMMA path everywhere).
//   s1: split x -> xa bf16 [8192 x 3072] ([hi|lo|hi])
//   s2/s3: transpose+split weights -> [N x 3K] bf16 ([hi|hi|lo])
//   k1: qkv GEMM (BK=32, 4-stage cp.async) -> split planes. Q pre-scaled.
//   k2: flash attention, 128 thr, 3 CTAs/SM (65.5KB smem): K double-buffered,
//       V single-buffered (hidden behind S+softmax), register-resident P,
//       Obuf aliased over Ka in epilogue -> augmented atta.
//   k3: out = atta @ wprojT^T + b_proj.
// ===========================================================================

#define EMBED   1024
#define HEADS   16
#define HDIM    64
#define BATCH   4
#define SEQ     2048
#define MROWS   (BATCH * SEQ)     // 8192
#define QKV_N   (3 * EMBED)       // 3072
#define KAUG    (3 * EMBED)       // 3072
#define NBH     (BATCH * HEADS)   // 64
#define QSC     (0.125f * 1.44269504f)

__device__ __nv_bfloat16  g_xa[(size_t)MROWS * KAUG];       // 48 MB
__device__ __nv_bfloat16  g_atta[(size_t)MROWS * KAUG];     // 48 MB
__device__ __nv_bfloat16  g_wqkvT[(size_t)QKV_N * KAUG];    // 18 MB
__device__ __nv_bfloat16  g_wprojT[(size_t)EMBED * KAUG];   //  6 MB
__device__ __nv_bfloat16  g_qhi[(size_t)NBH * SEQ * HDIM];
__device__ __nv_bfloat16  g_qlo[(size_t)NBH * SEQ * HDIM];
__device__ __nv_bfloat16  g_khi[(size_t)NBH * SEQ * HDIM];
__device__ __nv_bfloat16  g_klo[(size_t)NBH * SEQ * HDIM];
__device__ __nv_bfloat16  g_vhiT[(size_t)NBH * HDIM * SEQ];
__device__ __nv_bfloat16  g_vloT[(size_t)NBH * HDIM * SEQ];

// ---------------------------------------------------------------------------
// helpers
// ---------------------------------------------------------------------------
__device__ __forceinline__ uint32_t smem_u32(const void* p) {
    uint32_t a;
    asm("{ .reg .u64 t; cvta.to.shared.u64 t, %1; cvt.u32.u64 %0, t; }"
        : "=r"(a) : "l"(p));
    return a;
}
__device__ __forceinline__ void ldsm_x4(uint32_t& r0, uint32_t& r1,
                                        uint32_t& r2, uint32_t& r3, uint32_t addr) {
    asm volatile("ldmatrix.sync.aligned.m8n8.x4.shared.b16 {%0,%1,%2,%3}, [%4];"
                 : "=r"(r0), "=r"(r1), "=r"(r2), "=r"(r3) : "r"(addr));
}
__device__ __forceinline__ void mma_bf16(float* c, uint32_t a0, uint32_t a1,
                                         uint32_t a2, uint32_t a3,
                                         uint32_t b0, uint32_t b1) {
    asm volatile(
        "mma.sync.aligned.m16n8k16.row.col.f32.bf16.bf16.f32 "
        "{%0,%1,%2,%3}, {%4,%5,%6,%7}, {%8,%9}, {%0,%1,%2,%3};"
        : "+f"(c[0]), "+f"(c[1]), "+f"(c[2]), "+f"(c[3])
        : "r"(a0), "r"(a1), "r"(a2), "r"(a3), "r"(b0), "r"(b1));
}
#define CP_ASYNC16(smem, gptr) \
    asm volatile("cp.async.cg.shared.global [%0], [%1], 16;" :: "r"(smem), "l"(gptr))
#define CP_COMMIT() asm volatile("cp.async.commit_group;" ::: "memory")
#define CP_WAIT1()  asm volatile("cp.async.wait_group 1;" ::: "memory")
#define CP_WAIT2()  asm volatile("cp.async.wait_group 2;" ::: "memory")

// GEMM tile (64B rows): chunk' = chunk ^ ((row>>1)&3)
__device__ __forceinline__ uint32_t tile_off(int r, int c) {
    return (uint32_t)(r * 64 + ((c ^ ((r >> 1) & 3)) << 4));
}
// Flash tile (256B rows, 16 chunks): chunk' = chunk ^ (row & 7)
__device__ __forceinline__ uint32_t foff(int r, int c) {
    return (uint32_t)(r * 256 + ((c ^ (r & 7)) << 4));
}

__device__ __forceinline__ void split_hl(float v, __nv_bfloat16& hi, __nv_bfloat16& lo) {
    hi = __float2bfloat16_rn(v);
    lo = __float2bfloat16_rn(v - __bfloat162float(hi));
}
__device__ __forceinline__ uint32_t pack2bf(__nv_bfloat16 a, __nv_bfloat16 b) {
    __nv_bfloat162 p(a, b);
    return *reinterpret_cast<uint32_t*>(&p);
}
// pack high halves of two fp32 -> bf16x2 (truncation split)
__device__ __forceinline__ uint32_t prmt_hi(float a, float b) {
    return __byte_perm(__float_as_uint(a), __float_as_uint(b), 0x7632);
}
__device__ __forceinline__ float trunc_res(float v) {
    return v - __uint_as_float(__float_as_uint(v) & 0xFFFF0000u);
}

// ---------------------------------------------------------------------------
// s1: split x -> xa [hi | lo | hi]
// ---------------------------------------------------------------------------
__global__ void __launch_bounds__(256)
split_x_kernel(const float* __restrict__ x, __nv_bfloat16* __restrict__ xa)
{
    const int row = blockIdx.x;
    const int c = threadIdx.x * 4;
    float4 v = *(const float4*)(x + (size_t)row * EMBED + c);
    __nv_bfloat16 h0,h1,h2,h3,l0,l1,l2,l3;
    split_hl(v.x, h0, l0); split_hl(v.y, h1, l1);
    split_hl(v.z, h2, l2); split_hl(v.w, h3, l3);
    const size_t o = (size_t)row * KAUG + c;
    uint2 uh; uh.x = pack2bf(h0,h1); uh.y = pack2bf(h2,h3);
    uint2 ul; ul.x = pack2bf(l0,l1); ul.y = pack2bf(l2,l3);
    *(uint2*)(xa + o)           = uh;
    *(uint2*)(xa + o + EMBED)   = ul;
    *(uint2*)(xa + o + 2*EMBED) = uh;
}

// ---------------------------------------------------------------------------
// s2/s3: W [K x N] fp32 -> Bp [N x 3K] bf16 ([hi | hi | lo])
// ---------------------------------------------------------------------------
__global__ void __launch_bounds__(256)
transpose_split_kernel(const float* __restrict__ W, __nv_bfloat16* __restrict__ Bp,
                       int K, int N)
{
    __shared__ float t[32][33];
    const int n0 = blockIdx.x * 32, k0 = blockIdx.y * 32;
    const int tx = threadIdx.x, ty = threadIdx.y;
    #pragma unroll
    for (int i = 0; i < 4; ++i)
        t[ty + 8*i][tx] = W[(size_t)(k0 + ty + 8*i) * N + n0 + tx];
    __syncthreads();
    #pragma unroll
    for (int i = 0; i < 4; ++i) {
        const int n = ty + 8*i;
        float v = t[tx][n];
        __nv_bfloat16 hi, lo;
        split_hl(v, hi, lo);
        const size_t ro = (size_t)(n0 + n) * (3*K);
        Bp[ro + k0 + tx]       = hi;
        Bp[ro + K + k0 + tx]   = hi;
        Bp[ro + 2*K + k0 + tx] = lo;
    }
}

// ---------------------------------------------------------------------------
// HMMA GEMM (round-6 best): 128x128x32 tile, 8 warps (2x4), 4-stage cp.async.
// dyn smem = 4 x 16KB = 64KB.
// MODE 0: C = A@B^T + bias.  MODE 1: qkv epilogue -> split planes.
// ---------------------------------------------------------------------------
#define GEMM_SMEM 65536

template<int MODE>
__global__ void __launch_bounds__(256)
mma_gemm_kernel(const __nv_bfloat16* __restrict__ A, const __nv_bfloat16* __restrict__ B,
                const float* __restrict__ bias, float* __restrict__ C,
                __nv_bfloat16* __restrict__ qh, __nv_bfloat16* __restrict__ ql,
                __nv_bfloat16* __restrict__ kh, __nv_bfloat16* __restrict__ kl,
                __nv_bfloat16* __restrict__ vh, __nv_bfloat16* __restrict__ vl,
                int M, int N, int K)
{
    extern __shared__ __align__(1024) uint8_t dsm[];

    const int tid  = threadIdx.x;
    const int wid  = tid >> 5;
    const int lane = tid & 31;
    const int bx = blockIdx.x, by = blockIdx.y;
    const int warp_m = wid & 1;
    const int warp_n = wid >> 1;
    const uint32_t sbase = smem_u32(dsm);

    const size_t Ks = (size_t)K;
    const __nv_bfloat16* Ab = A + (size_t)(by * 128) * Ks;
    const __nv_bfloat16* Bb = B + (size_t)(bx * 128) * Ks;

    const int lr0 = tid >> 2,         lc0 = tid & 3;
    const int lr1 = (tid + 256) >> 2, lc1 = (tid + 256) & 3;
    const __nv_bfloat16* Ag0 = Ab + (size_t)lr0 * Ks + lc0 * 8;
    const __nv_bfloat16* Ag1 = Ab + (size_t)lr1 * Ks + lc1 * 8;
    const __nv_bfloat16* Bg0 = Bb + (size_t)lr0 * Ks + lc0 * 8;
    const __nv_bfloat16* Bg1 = Bb + (size_t)lr1 * Ks + lc1 * 8;
    const uint32_t sA0 = tile_off(lr0, lc0), sA1 = tile_off(lr1, lc1);

    auto load_stage = [&](int kt, int st) {
        const int k0 = kt * 32;
        const uint32_t s = sbase + st * 16384;
        CP_ASYNC16(s + sA0,        Ag0 + k0);
        CP_ASYNC16(s + sA1,        Ag1 + k0);
        CP_ASYNC16(s + 8192 + sA0, Bg0 + k0);
        CP_ASYNC16(s + 8192 + sA1, Bg1 + k0);
    };

    uint32_t aoff[2][4], boff[2][2];
    #pragma unroll
    for (int ks = 0; ks < 2; ++ks) {
        #pragma unroll
        for (int mf = 0; mf < 4; ++mf)
            aoff[ks][mf] = tile_off(warp_m * 64 + mf * 16 + (lane & 15),
                                    ks * 2 + (lane >> 4));
        #pragma unroll
        for (int np = 0; np < 2; ++np)
            boff[ks][np] = 8192 + tile_off(warp_n * 32 + np * 16 + (lane & 15),
                                           ks * 2 + (lane >> 4));
    }

    float acc[4][4][4] = {};
    const int T = K >> 5;      // 96

    load_stage(0, 0); CP_COMMIT();
    load_stage(1, 1); CP_COMMIT();
    load_stage(2, 2); CP_COMMIT();

    for (int t = 0; t < T; ++t) {
        CP_WAIT2();
        __syncthreads();

        const uint32_t st = sbase + (t & 3) * 16384;
        #pragma unroll
        for (int ks = 0; ks < 2; ++ks) {
            uint32_t a[4][4];
            #pragma unroll
            for (int mf = 0; mf < 4; ++mf)
                ldsm_x4(a[mf][0], a[mf][1], a[mf][2], a[mf][3], st + aoff[ks][mf]);
            uint32_t b[2][4];
            #pragma unroll
            for (int np = 0; np < 2; ++np)
                ldsm_x4(b[np][0], b[np][1], b[np][2], b[np][3], st + boff[ks][np]);
            #pragma unroll
            for (int mf = 0; mf < 4; ++mf)
                #pragma unroll
                for (int nf = 0; nf < 4; ++nf) {
                    const int np = nf >> 1, hl = nf & 1;
                    mma_bf16(acc[mf][nf], a[mf][0], a[mf][1], a[mf][2], a[mf][3],
                             b[np][0 + hl], b[np][2 + hl]);
                }
        }

        if (t + 3 < T) load_stage(t + 3, (t + 3) & 3);
        CP_COMMIT();
    }

    const int g  = lane >> 2;
    const int cl = (lane & 3) * 2;
    #pragma unroll
    for (int mf = 0; mf < 4; ++mf) {
        const int mrow = by * 128 + warp_m * 64 + mf * 16 + g;
        #pragma unroll
        for (int nf = 0; nf < 4; ++nf) {
            const int col = bx * 128 + warp_n * 32 + nf * 8 + cl;
            const float b0 = bias[col], b1 = bias[col + 1];
            float v[4] = { acc[mf][nf][0] + b0, acc[mf][nf][1] + b1,
                           acc[mf][nf][2] + b0, acc[mf][nf][3] + b1 };
            if constexpr (MODE == 0) {
                *(float2*)(C + (size_t)mrow * N + col)       = make_float2(v[0], v[1]);
                *(float2*)(C + (size_t)(mrow + 8) * N + col) = make_float2(v[2], v[3]);
            } else {
                const int which = col >> 10;           // 0=q 1=k 2=v
                const int h = (col >> 6) & 15;
                const int d = col & 63;
                const int bb = mrow >> 11;
                const int n0 = mrow & 2047;
                if (which == 0) { v[0]*=QSC; v[1]*=QSC; v[2]*=QSC; v[3]*=QSC; }
                #pragma unroll
                for (int rr = 0; rr < 2; ++rr) {
                    const int n = n0 + rr * 8;
                    __nv_bfloat16 h0,l0,h1,l1;
                    split_hl(v[rr*2+0], h0, l0);
                    split_hl(v[rr*2+1], h1, l1);
                    if (which < 2) {
                        const size_t base = (size_t)(bb*16 + h) * (SEQ*HDIM)
                                          + (size_t)n * HDIM + d;
                        __nv_bfloat16* PH = which ? kh : qh;
                        __nv_bfloat16* PL = which ? kl : ql;
                        *(uint32_t*)(PH + base) = pack2bf(h0, h1);
                        *(uint32_t*)(PL + base) = pack2bf(l0, l1);
                    } else {
                        const size_t base = (size_t)(bb*16 + h) * (SEQ*HDIM)
                                          + (size_t)d * SEQ + n;
                        vh[base]       = h0;  vh[base + SEQ] = h1;
                        vl[base]       = l0;  vl[base + SEQ] = l1;
                    }
                }
            }
        }
    }
}

// ---------------------------------------------------------------------------
// k2: flash attention, 128 thr (4 warps 2x2), 3 CTAs/SM target.
// smem: Qa 16K | Ka[2] 32K | Va 16K | stats 1.5K = 67072 B (Obuf aliases Ka).
// K double-buffered; V single-buffered (load hidden behind S+softmax).
// P register-resident (PRMT split); warpN splits keys in PV; O pair-reduced
// through Ka-aliased Obuf in epilogue.
// ---------------------------------------------------------------------------
#define FLASH_SMEM (65536 + 1536)

__global__ void __launch_bounds__(128, 3)
flash_mma_kernel(const __nv_bfloat16* __restrict__ qhi, const __nv_bfloat16* __restrict__ qlo,
                 const __nv_bfloat16* __restrict__ khi, const __nv_bfloat16* __restrict__ klo,
                 const __nv_bfloat16* __restrict__ vhiT, const __nv_bfloat16* __restrict__ vloT,
                 __nv_bfloat16* __restrict__ atta)
{
    extern __shared__ __align__(1024) uint8_t fsm[];
    float* Obuf = (float*)(fsm + 16384);     // aliases Ka (epilogue only)
    float* pmax = (float*)(fsm + 65536);     // [2][64]
    float* psum = pmax + 128;                // [2][64]
    float* m_s  = psum + 128;                // [64]
    float* l_s  = m_s + 64;                  // [64]

    const uint32_t sbase = smem_u32(fsm);
    const uint32_t qa_u  = sbase;
    const uint32_t ka_u0 = sbase + 16384;    // + buf*16384
    const uint32_t va_u  = sbase + 49152;

    const int tid  = threadIdx.x;
    const int wid  = tid >> 5;
    const int lane = tid & 31;
    const int warpM = wid >> 1;
    const int warpN = wid & 1;
    const int g  = lane >> 2;
    const int qd = lane & 3;
    const int rlo = lane & 15, hi = lane >> 4;

    const int qt = blockIdx.x, bh = blockIdx.y;
    const int q0 = qt * 64;

    // Q load (group 1)
    {
        const size_t qbase = ((size_t)bh * SEQ + q0) * HDIM;
        for (int i = tid; i < 1024; i += 128) {
            const int r = i >> 4, c = i & 15;
            CP_ASYNC16(qa_u + foff(r, c),
                       (c < 8 ? qhi : qlo) + qbase + r * HDIM + (c & 7) * 8);
        }
        CP_COMMIT();
    }

    auto load_k = [&](int kt, int buf) {
        const size_t kbase = ((size_t)bh * SEQ + kt * 64) * HDIM;
        const uint32_t ka = ka_u0 + buf * 16384;
        for (int i = tid; i < 1024; i += 128) {
            const int r = i >> 4, c = i & 15;
            CP_ASYNC16(ka + foff(r, c),
                       (c < 8 ? khi : klo) + kbase + r * HDIM + (c & 7) * 8);
        }
    };
    auto load_v = [&](int kt) {
        for (int i = tid; i < 1024; i += 128) {
            const int r = i >> 4, c = i & 15;
            CP_ASYNC16(va_u + foff(r, c),
                       (c < 8 ? vhiT : vloT) + (size_t)(bh * HDIM + r) * SEQ
                                             + kt * 64 + (c & 7) * 8);
        }
    };

    load_k(0, 0); CP_COMMIT();               // group 2
    if (tid < 64) { m_s[tid] = -1e30f; l_s[tid] = 0.f; }

    auto update_stats = [&]() {
        #pragma unroll
        for (int m = 0; m < 2; ++m)
            #pragma unroll
            for (int gg = 0; gg < 2; ++gg) {
                const int r = warpM*32 + m*16 + g + gg*8;
                const float mx = fmaxf(pmax[r], pmax[64 + r]);
                const float mo = m_s[r];
                const float mn = fmaxf(mo, mx);
                l_s[r] = l_s[r] * exp2f(mo - mn) + psum[r] + psum[64 + r];
                m_s[r] = mn;
            }
    };

    float oacc[2][8][4] = {};   // [m][d-tile][reg]

    for (int kt = 0; kt < 32; ++kt) {
        const int buf = kt & 1;
        __syncthreads();              // (a) prior iter fully done (Va, ka[buf^..])
        if (kt > 0 && warpN == 0 && qd == 0) update_stats();
        load_v(kt); CP_COMMIT();
        if (kt + 1 < 32) load_k(kt + 1, buf ^ 1);
        CP_COMMIT();                  // (possibly empty) K group keeps ledger uniform
        CP_WAIT2();                   // K(kt) (and Q on iter 0) landed
        __syncthreads();              // (b) everyone's K(kt) visible

        const uint32_t ka_u = ka_u0 + buf * 16384;

        // ---- S = Qhi.Khi + Qlo.Khi + Qhi.Klo, per-unit fragment reuse ----
        float sacc[2][4][4] = {};
        #pragma unroll
        for (int u = 0; u < 4; ++u) {
            uint32_t ah[2][4], al[2][4], bh_[2][4], bl[2][4];
            #pragma unroll
            for (int m = 0; m < 2; ++m) {
                ldsm_x4(ah[m][0], ah[m][1], ah[m][2], ah[m][3],
                        qa_u + foff(warpM*32 + m*16 + rlo, 2*u + hi));
                ldsm_x4(al[m][0], al[m][1], al[m][2], al[m][3],
                        qa_u + foff(warpM*32 + m*16 + rlo, 2*(u+4) + hi));
            }
            #pragma unroll
            for (int np = 0; np < 2; ++np) {
                ldsm_x4(bh_[np][0], bh_[np][1], bh_[np][2], bh_[np][3],
                        ka_u + foff(warpN*32 + np*16 + rlo, 2*u + hi));
                ldsm_x4(bl[np][0], bl[np][1], bl[np][2], bl[np][3],
                        ka_u + foff(warpN*32 + np*16 + rlo, 2*(u+4) + hi));
            }
            #pragma unroll
            for (int m = 0; m < 2; ++m)
                #pragma unroll
                for (int nf = 0; nf < 4; ++nf) {
                    const int np = nf >> 1, hl = nf & 1;
                    mma_bf16(sacc[m][nf], ah[m][0], ah[m][1], ah[m][2], ah[m][3],
                             bh_[np][0 + hl], bh_[np][2 + hl]);
                    mma_bf16(sacc[m][nf], al[m][0], al[m][1], al[m][2], al[m][3],
                             bh_[np][0 + hl], bh_[np][2 + hl]);
                    mma_bf16(sacc[m][nf], ah[m][0], ah[m][1], ah[m][2], ah[m][3],
                             bl[np][0 + hl], bl[np][2 + hl]);
                }
        }

        // ---- row-max ----
        float tmax[2][2];
        #pragma unroll
        for (int m = 0; m < 2; ++m)
            #pragma unroll
            for (int gg = 0; gg < 2; ++gg) {
                float mx = -1e30f;
                #pragma unroll
                for (int nf = 0; nf < 4; ++nf)
                    mx = fmaxf(mx, fmaxf(sacc[m][nf][gg*2], sacc[m][nf][gg*2+1]));
                tmax[m][gg] = mx;
            }
        #pragma unroll
        for (int o = 1; o <= 2; o <<= 1)
            #pragma unroll
            for (int m = 0; m < 2; ++m)
                #pragma unroll
                for (int gg = 0; gg < 2; ++gg)
                    tmax[m][gg] = fmaxf(tmax[m][gg],
                                        __shfl_xor_sync(0xffffffffu, tmax[m][gg], o));
        if (qd == 0)
            #pragma unroll
            for (int m = 0; m < 2; ++m)
                #pragma unroll
                for (int gg = 0; gg < 2; ++gg)
                    pmax[warpN*64 + warpM*32 + m*16 + g + gg*8] = tmax[m][gg];
        CP_WAIT1();                   // V(kt) landed (K(kt+1) may still fly)
        __syncthreads();              // (c): pmax visible + everyone's V visible

        // ---- softmax: exp2 overwrites sacc; psum; rescale O ----
        float corr[2][2], tsum[2][2];
        #pragma unroll
        for (int m = 0; m < 2; ++m)
            #pragma unroll
            for (int gg = 0; gg < 2; ++gg) {
                const int r = warpM*32 + m*16 + g + gg*8;
                const float mx = fmaxf(pmax[r], pmax[64 + r]);
                const float mo = m_s[r];
                const float mn = fmaxf(mo, mx);
                corr[m][gg] = exp2f(mo - mn);
                float sum = 0.f;
                #pragma unroll
                for (int nf = 0; nf < 4; ++nf) {
                    const float p0 = exp2f(sacc[m][nf][gg*2]   - mn);
                    const float p1 = exp2f(sacc[m][nf][gg*2+1] - mn);
                    sacc[m][nf][gg*2]   = p0;
                    sacc[m][nf][gg*2+1] = p1;
                    sum += p0 + p1;
                }
                tsum[m][gg] = sum;
            }
        #pragma unroll
        for (int o = 1; o <= 2; o <<= 1)
            #pragma unroll
            for (int m = 0; m < 2; ++m)
                #pragma unroll
                for (int gg = 0; gg < 2; ++gg)
                    tsum[m][gg] += __shfl_xor_sync(0xffffffffu, tsum[m][gg], o);
        if (qd == 0)
            #pragma unroll
            for (int m = 0; m < 2; ++m)
                #pragma unroll
                for (int gg = 0; gg < 2; ++gg)
                    psum[warpN*64 + warpM*32 + m*16 + g + gg*8] = tsum[m][gg];
        #pragma unroll
        for (int m = 0; m < 2; ++m)
            #pragma unroll
            for (int nf = 0; nf < 8; ++nf) {
                oacc[m][nf][0] *= corr[m][0];
                oacc[m][nf][1] *= corr[m][0];
                oacc[m][nf][2] *= corr[m][1];
                oacc[m][nf][3] *= corr[m][1];
            }

        // ---- PV: O += Phi.Vhi + Plo.Vhi + Phi.Vlo (pack per-ku from sacc) ----
        #pragma unroll
        for (int ku = 0; ku < 2; ++ku) {
            uint32_t phi[2][4], plo[2][4];
            #pragma unroll
            for (int m = 0; m < 2; ++m) {
                const int nf0 = 2*ku, nf1 = 2*ku + 1;
                phi[m][0] = prmt_hi(sacc[m][nf0][0], sacc[m][nf0][1]);
                phi[m][1] = prmt_hi(sacc[m][nf0][2], sacc[m][nf0][3]);
                phi[m][2] = prmt_hi(sacc[m][nf1][0], sacc[m][nf1][1]);
                phi[m][3] = prmt_hi(sacc[m][nf1][2], sacc[m][nf1][3]);
                plo[m][0] = prmt_hi(trunc_res(sacc[m][nf0][0]), trunc_res(sacc[m][nf0][1]));
                plo[m][1] = prmt_hi(trunc_res(sacc[m][nf0][2]), trunc_res(sacc[m][nf0][3]));
                plo[m][2] = prmt_hi(trunc_res(sacc[m][nf1][0]), trunc_res(sacc[m][nf1][1]));
                plo[m][3] = prmt_hi(trunc_res(sacc[m][nf1][2]), trunc_res(sacc[m][nf1][3]));
            }
            uint32_t vh_[4][4], vl_[4][4];
            #pragma unroll
            for (int j = 0; j < 4; ++j) {
                ldsm_x4(vh_[j][0], vh_[j][1], vh_[j][2], vh_[j][3],
                        va_u + foff(j*16 + rlo, 2*(warpN*2 + ku) + hi));
                ldsm_x4(vl_[j][0], vl_[j][1], vl_[j][2], vl_[j][3],
                        va_u + foff(j*16 + rlo, 2*(4 + warpN*2 + ku) + hi));
            }
            #pragma unroll
            for (int m = 0; m < 2; ++m)
                #pragma unroll
                for (int j = 0; j < 4; ++j)
                    #pragma unroll
                    for (int hl = 0; hl < 2; ++hl) {
                        const int nf_o = j*2 + hl;
                        mma_bf16(oacc[m][nf_o], phi[m][0], phi[m][1],
                                 phi[m][2], phi[m][3],
                                 vh_[j][hl], vh_[j][2 + hl]);
                        mma_bf16(oacc[m][nf_o], plo[m][0], plo[m][1],
                                 plo[m][2], plo[m][3],
                                 vh_[j][hl], vh_[j][2 + hl]);
                        mma_bf16(oacc[m][nf_o], phi[m][0], phi[m][1],
                                 phi[m][2], phi[m][3],
                                 vl_[j][hl], vl_[j][2 + hl]);
                    }
        }
    }

    // final stats + cross-warpN O reduction (Obuf aliases Ka, dead now) + write
    __syncthreads();
    if (warpN == 0 && qd == 0) update_stats();
    if (warpN == 1) {
        #pragma unroll
        for (int m = 0; m < 2; ++m)
            #pragma unroll
            for (int nf = 0; nf < 8; ++nf)
                #pragma unroll
                for (int gg = 0; gg < 2; ++gg) {
                    float* dst = Obuf + warpM*2048 + (m*16 + g + gg*8)*64 + nf*8 + qd*2;
                    *(float2*)dst = make_float2(oacc[m][nf][gg*2], oacc[m][nf][gg*2+1]);
                }
    }
    __syncthreads();

    if (warpN == 0) {
        const int b_ = bh >> 4, h = bh & 15;
        float inv[2][2];
        #pragma unroll
        for (int m = 0; m < 2; ++m)
            #pragma unroll
            for (int gg = 0; gg < 2; ++gg)
                inv[m][gg] = 1.f / l_s[warpM*32 + m*16 + g + gg*8];

        #pragma unroll
        for (int m = 0; m < 2; ++m)
            #pragma unroll
            for (int nf = 0; nf < 8; ++nf)
                #pragma unroll
                for (int gg = 0; gg < 2; ++gg) {
                    const int r = warpM*32 + m*16 + g + gg*8;
                    const float* src = Obuf + warpM*2048 + (m*16 + g + gg*8)*64 + nf*8 + qd*2;
                    float2 o2 = *(const float2*)src;
                    const float v0 = (oacc[m][nf][gg*2]   + o2.x) * inv[m][gg];
                    const float v1 = (oacc[m][nf][gg*2+1] + o2.y) * inv[m][gg];
                    __nv_bfloat16 h0,l0,h1,l1;
                    split_hl(v0, h0, l0);
                    split_hl(v1, h1, l1);
                    const size_t ro = (size_t)(b_*SEQ + q0 + r) * KAUG + h*64 + nf*8 + qd*2;
                    *(uint32_t*)(atta + ro)            = pack2bf(h0, h1);
                    *(uint32_t*)(atta + ro + EMBED)    = pack2bf(l0, l1);
                    *(uint32_t*)(atta + ro + 2*EMBED)  = pack2bf(h0, h1);
                }
    }
}

// ---------------------------------------------------------------------------
// Launch
// ---------------------------------------------------------------------------
extern "C" void kernel_launch(void* const* d_in, const int* in_sizes, int n_in,
                              void* d_out, int out_size)
{
    const float* x      = (const float*)d_in[0];
    const float* w_qkv  = (const float*)d_in[1];
    const float* b_qkv  = (const float*)d_in[2];
    const float* w_proj = (const float*)d_in[3];
    const float* b_proj = (const float*)d_in[4];
    float* out = (float*)d_out;

    __nv_bfloat16 *xa, *atta, *wqkvT, *wprojT, *qh, *ql, *kh, *kl, *vh, *vl;
    cudaGetSymbolAddress((void**)&xa,     g_xa);
    cudaGetSymbolAddress((void**)&atta,   g_atta);
    cudaGetSymbolAddress((void**)&wqkvT,  g_wqkvT);
    cudaGetSymbolAddress((void**)&wprojT, g_wprojT);
    cudaGetSymbolAddress((void**)&qh,     g_qhi);
    cudaGetSymbolAddress((void**)&ql,     g_qlo);
    cudaGetSymbolAddress((void**)&kh,     g_khi);
    cudaGetSymbolAddress((void**)&kl,     g_klo);
    cudaGetSymbolAddress((void**)&vh,     g_vhiT);
    cudaGetSymbolAddress((void**)&vl,     g_vloT);

    cudaFuncSetAttribute(mma_gemm_kernel<1>,
                         cudaFuncAttributeMaxDynamicSharedMemorySize, GEMM_SMEM);
    cudaFuncSetAttribute(mma_gemm_kernel<0>,
                         cudaFuncAttributeMaxDynamicSharedMemorySize, GEMM_SMEM);
    cudaFuncSetAttribute(flash_mma_kernel,
                         cudaFuncAttributeMaxDynamicSharedMemorySize, FLASH_SMEM);

    split_x_kernel<<<MROWS, 256>>>(x, xa);
    transpose_split_kernel<<<dim3(QKV_N/32, EMBED/32), dim3(32,8)>>>(w_qkv, wqkvT, EMBED, QKV_N);
    transpose_split_kernel<<<dim3(EMBED/32, EMBED/32), dim3(32,8)>>>(w_proj, wprojT, EMBED, EMBED);

    mma_gemm_kernel<1><<<dim3(QKV_N/128, MROWS/128), 256, GEMM_SMEM>>>(
        xa, wqkvT, b_qkv, nullptr, qh, ql, kh, kl, vh, vl, MROWS, QKV_N, KAUG);

    flash_mma_kernel<<<dim3(SEQ/64, NBH), 128, FLASH_SMEM>>>(qh, ql, kh, kl, vh, vl, atta);

    mma_gemm_kernel<0><<<dim3(EMBED/128, MROWS/128), 256, GEMM_SMEM>>>(
        atta, wprojT, b_proj, out, nullptr, nullptr, nullptr, nullptr, nullptr, nullptr,
        MROWS, EMBED, KAUG);
}

// round 14
// speedup vs baseline: 1.1618x; 1.0452x over previous
#include <cuda_runtime.h>
#include <cuda_bf16.h>
#include <cstdint>

// ===========================================================================
// MultiHeadSelfAttention, sm_100 (mma.sync HMMA path everywhere).
//   s1: split x -> xa bf16 [8192 x 3072] ([hi|lo|hi])
//   s2/s3: transpose+split weights -> [N x 3K] bf16 ([hi|hi|lo])
//   k1: qkv GEMM (BK=32, 4-stage cp.async) -> split planes. Q pre-scaled.
//   k2: flash attention FA2-style: each warp owns 16 query rows x all keys;
//       fully warp-local softmax (register stats), register-resident P,
//       K double-buffered, V single-buffered. 3 CTAs/SM. -> augmented atta.
//   k3: out = atta @ wprojT^T + b_proj.
// ===========================================================================

#define EMBED   1024
#define HEADS   16
#define HDIM    64
#define BATCH   4
#define SEQ     2048
#define MROWS   (BATCH * SEQ)     // 8192
#define QKV_N   (3 * EMBED)       // 3072
#define KAUG    (3 * EMBED)       // 3072
#define NBH     (BATCH * HEADS)   // 64
#define QSC     (0.125f * 1.44269504f)

__device__ __nv_bfloat16  g_xa[(size_t)MROWS * KAUG];       // 48 MB
__device__ __nv_bfloat16  g_atta[(size_t)MROWS * KAUG];     // 48 MB
__device__ __nv_bfloat16  g_wqkvT[(size_t)QKV_N * KAUG];    // 18 MB
__device__ __nv_bfloat16  g_wprojT[(size_t)EMBED * KAUG];   //  6 MB
__device__ __nv_bfloat16  g_qhi[(size_t)NBH * SEQ * HDIM];
__device__ __nv_bfloat16  g_qlo[(size_t)NBH * SEQ * HDIM];
__device__ __nv_bfloat16  g_khi[(size_t)NBH * SEQ * HDIM];
__device__ __nv_bfloat16  g_klo[(size_t)NBH * SEQ * HDIM];
__device__ __nv_bfloat16  g_vhiT[(size_t)NBH * HDIM * SEQ];
__device__ __nv_bfloat16  g_vloT[(size_t)NBH * HDIM * SEQ];

// ---------------------------------------------------------------------------
// helpers
// ---------------------------------------------------------------------------
__device__ __forceinline__ uint32_t smem_u32(const void* p) {
    uint32_t a;
    asm("{ .reg .u64 t; cvta.to.shared.u64 t, %1; cvt.u32.u64 %0, t; }"
        : "=r"(a) : "l"(p));
    return a;
}
__device__ __forceinline__ void ldsm_x4(uint32_t& r0, uint32_t& r1,
                                        uint32_t& r2, uint32_t& r3, uint32_t addr) {
    asm volatile("ldmatrix.sync.aligned.m8n8.x4.shared.b16 {%0,%1,%2,%3}, [%4];"
                 : "=r"(r0), "=r"(r1), "=r"(r2), "=r"(r3) : "r"(addr));
}
__device__ __forceinline__ void mma_bf16(float* c, uint32_t a0, uint32_t a1,
                                         uint32_t a2, uint32_t a3,
                                         uint32_t b0, uint32_t b1) {
    asm volatile(
        "mma.sync.aligned.m16n8k16.row.col.f32.bf16.bf16.f32 "
        "{%0,%1,%2,%3}, {%4,%5,%6,%7}, {%8,%9}, {%0,%1,%2,%3};"
        : "+f"(c[0]), "+f"(c[1]), "+f"(c[2]), "+f"(c[3])
        : "r"(a0), "r"(a1), "r"(a2), "r"(a3), "r"(b0), "r"(b1));
}
#define CP_ASYNC16(smem, gptr) \
    asm volatile("cp.async.cg.shared.global [%0], [%1], 16;" :: "r"(smem), "l"(gptr))
#define CP_COMMIT() asm volatile("cp.async.commit_group;" ::: "memory")
#define CP_WAIT1()  asm volatile("cp.async.wait_group 1;" ::: "memory")
#define CP_WAIT2()  asm volatile("cp.async.wait_group 2;" ::: "memory")

// GEMM tile (64B rows): chunk' = chunk ^ ((row>>1)&3)
__device__ __forceinline__ uint32_t tile_off(int r, int c) {
    return (uint32_t)(r * 64 + ((c ^ ((r >> 1) & 3)) << 4));
}
// Flash tile (256B rows, 16 chunks): chunk' = chunk ^ (row & 7)
__device__ __forceinline__ uint32_t foff(int r, int c) {
    return (uint32_t)(r * 256 + ((c ^ (r & 7)) << 4));
}

__device__ __forceinline__ void split_hl(float v, __nv_bfloat16& hi, __nv_bfloat16& lo) {
    hi = __float2bfloat16_rn(v);
    lo = __float2bfloat16_rn(v - __bfloat162float(hi));
}
__device__ __forceinline__ uint32_t pack2bf(__nv_bfloat16 a, __nv_bfloat16 b) {
    __nv_bfloat162 p(a, b);
    return *reinterpret_cast<uint32_t*>(&p);
}
// pack high halves of two fp32 -> bf16x2 (truncation split)
__device__ __forceinline__ uint32_t prmt_hi(float a, float b) {
    return __byte_perm(__float_as_uint(a), __float_as_uint(b), 0x7632);
}
__device__ __forceinline__ float trunc_res(float v) {
    return v - __uint_as_float(__float_as_uint(v) & 0xFFFF0000u);
}

// ---------------------------------------------------------------------------
// s1: split x -> xa [hi | lo | hi]
// ---------------------------------------------------------------------------
__global__ void __launch_bounds__(256)
split_x_kernel(const float* __restrict__ x, __nv_bfloat16* __restrict__ xa)
{
    const int row = blockIdx.x;
    const int c = threadIdx.x * 4;
    float4 v = *(const float4*)(x + (size_t)row * EMBED + c);
    __nv_bfloat16 h0,h1,h2,h3,l0,l1,l2,l3;
    split_hl(v.x, h0, l0); split_hl(v.y, h1, l1);
    split_hl(v.z, h2, l2); split_hl(v.w, h3, l3);
    const size_t o = (size_t)row * KAUG + c;
    uint2 uh; uh.x = pack2bf(h0,h1); uh.y = pack2bf(h2,h3);
    uint2 ul; ul.x = pack2bf(l0,l1); ul.y = pack2bf(l2,l3);
    *(uint2*)(xa + o)           = uh;
    *(uint2*)(xa + o + EMBED)   = ul;
    *(uint2*)(xa + o + 2*EMBED) = uh;
}

// ---------------------------------------------------------------------------
// s2/s3: W [K x N] fp32 -> Bp [N x 3K] bf16 ([hi | hi | lo])
// ---------------------------------------------------------------------------
__global__ void __launch_bounds__(256)
transpose_split_kernel(const float* __restrict__ W, __nv_bfloat16* __restrict__ Bp,
                       int K, int N)
{
    __shared__ float t[32][33];
    const int n0 = blockIdx.x * 32, k0 = blockIdx.y * 32;
    const int tx = threadIdx.x, ty = threadIdx.y;
    #pragma unroll
    for (int i = 0; i < 4; ++i)
        t[ty + 8*i][tx] = W[(size_t)(k0 + ty + 8*i) * N + n0 + tx];
    __syncthreads();
    #pragma unroll
    for (int i = 0; i < 4; ++i) {
        const int n = ty + 8*i;
        float v = t[tx][n];
        __nv_bfloat16 hi, lo;
        split_hl(v, hi, lo);
        const size_t ro = (size_t)(n0 + n) * (3*K);
        Bp[ro + k0 + tx]       = hi;
        Bp[ro + K + k0 + tx]   = hi;
        Bp[ro + 2*K + k0 + tx] = lo;
    }
}

// ---------------------------------------------------------------------------
// HMMA GEMM (round-6 best): 128x128x32 tile, 8 warps (2x4), 4-stage cp.async.
// dyn smem = 4 x 16KB = 64KB.
// MODE 0: C = A@B^T + bias.  MODE 1: qkv epilogue -> split planes.
// ---------------------------------------------------------------------------
#define GEMM_SMEM 65536

template<int MODE>
__global__ void __launch_bounds__(256)
mma_gemm_kernel(const __nv_bfloat16* __restrict__ A, const __nv_bfloat16* __restrict__ B,
                const float* __restrict__ bias, float* __restrict__ C,
                __nv_bfloat16* __restrict__ qh, __nv_bfloat16* __restrict__ ql,
                __nv_bfloat16* __restrict__ kh, __nv_bfloat16* __restrict__ kl,
                __nv_bfloat16* __restrict__ vh, __nv_bfloat16* __restrict__ vl,
                int M, int N, int K)
{
    extern __shared__ __align__(1024) uint8_t dsm[];

    const int tid  = threadIdx.x;
    const int wid  = tid >> 5;
    const int lane = tid & 31;
    const int bx = blockIdx.x, by = blockIdx.y;
    const int warp_m = wid & 1;
    const int warp_n = wid >> 1;
    const uint32_t sbase = smem_u32(dsm);

    const size_t Ks = (size_t)K;
    const __nv_bfloat16* Ab = A + (size_t)(by * 128) * Ks;
    const __nv_bfloat16* Bb = B + (size_t)(bx * 128) * Ks;

    const int lr0 = tid >> 2,         lc0 = tid & 3;
    const int lr1 = (tid + 256) >> 2, lc1 = (tid + 256) & 3;
    const __nv_bfloat16* Ag0 = Ab + (size_t)lr0 * Ks + lc0 * 8;
    const __nv_bfloat16* Ag1 = Ab + (size_t)lr1 * Ks + lc1 * 8;
    const __nv_bfloat16* Bg0 = Bb + (size_t)lr0 * Ks + lc0 * 8;
    const __nv_bfloat16* Bg1 = Bb + (size_t)lr1 * Ks + lc1 * 8;
    const uint32_t sA0 = tile_off(lr0, lc0), sA1 = tile_off(lr1, lc1);

    auto load_stage = [&](int kt, int st) {
        const int k0 = kt * 32;
        const uint32_t s = sbase + st * 16384;
        CP_ASYNC16(s + sA0,        Ag0 + k0);
        CP_ASYNC16(s + sA1,        Ag1 + k0);
        CP_ASYNC16(s + 8192 + sA0, Bg0 + k0);
        CP_ASYNC16(s + 8192 + sA1, Bg1 + k0);
    };

    uint32_t aoff[2][4], boff[2][2];
    #pragma unroll
    for (int ks = 0; ks < 2; ++ks) {
        #pragma unroll
        for (int mf = 0; mf < 4; ++mf)
            aoff[ks][mf] = tile_off(warp_m * 64 + mf * 16 + (lane & 15),
                                    ks * 2 + (lane >> 4));
        #pragma unroll
        for (int np = 0; np < 2; ++np)
            boff[ks][np] = 8192 + tile_off(warp_n * 32 + np * 16 + (lane & 15),
                                           ks * 2 + (lane >> 4));
    }

    float acc[4][4][4] = {};
    const int T = K >> 5;      // 96

    load_stage(0, 0); CP_COMMIT();
    load_stage(1, 1); CP_COMMIT();
    load_stage(2, 2); CP_COMMIT();

    for (int t = 0; t < T; ++t) {
        CP_WAIT2();
        __syncthreads();

        const uint32_t st = sbase + (t & 3) * 16384;
        #pragma unroll
        for (int ks = 0; ks < 2; ++ks) {
            uint32_t a[4][4];
            #pragma unroll
            for (int mf = 0; mf < 4; ++mf)
                ldsm_x4(a[mf][0], a[mf][1], a[mf][2], a[mf][3], st + aoff[ks][mf]);
            uint32_t b[2][4];
            #pragma unroll
            for (int np = 0; np < 2; ++np)
                ldsm_x4(b[np][0], b[np][1], b[np][2], b[np][3], st + boff[ks][np]);
            #pragma unroll
            for (int mf = 0; mf < 4; ++mf)
                #pragma unroll
                for (int nf = 0; nf < 4; ++nf) {
                    const int np = nf >> 1, hl = nf & 1;
                    mma_bf16(acc[mf][nf], a[mf][0], a[mf][1], a[mf][2], a[mf][3],
                             b[np][0 + hl], b[np][2 + hl]);
                }
        }

        if (t + 3 < T) load_stage(t + 3, (t + 3) & 3);
        CP_COMMIT();
    }

    const int g  = lane >> 2;
    const int cl = (lane & 3) * 2;
    #pragma unroll
    for (int mf = 0; mf < 4; ++mf) {
        const int mrow = by * 128 + warp_m * 64 + mf * 16 + g;
        #pragma unroll
        for (int nf = 0; nf < 4; ++nf) {
            const int col = bx * 128 + warp_n * 32 + nf * 8 + cl;
            const float b0 = bias[col], b1 = bias[col + 1];
            float v[4] = { acc[mf][nf][0] + b0, acc[mf][nf][1] + b1,
                           acc[mf][nf][2] + b0, acc[mf][nf][3] + b1 };
            if constexpr (MODE == 0) {
                *(float2*)(C + (size_t)mrow * N + col)       = make_float2(v[0], v[1]);
                *(float2*)(C + (size_t)(mrow + 8) * N + col) = make_float2(v[2], v[3]);
            } else {
                const int which = col >> 10;           // 0=q 1=k 2=v
                const int h = (col >> 6) & 15;
                const int d = col & 63;
                const int bb = mrow >> 11;
                const int n0 = mrow & 2047;
                if (which == 0) { v[0]*=QSC; v[1]*=QSC; v[2]*=QSC; v[3]*=QSC; }
                #pragma unroll
                for (int rr = 0; rr < 2; ++rr) {
                    const int n = n0 + rr * 8;
                    __nv_bfloat16 h0,l0,h1,l1;
                    split_hl(v[rr*2+0], h0, l0);
                    split_hl(v[rr*2+1], h1, l1);
                    if (which < 2) {
                        const size_t base = (size_t)(bb*16 + h) * (SEQ*HDIM)
                                          + (size_t)n * HDIM + d;
                        __nv_bfloat16* PH = which ? kh : qh;
                        __nv_bfloat16* PL = which ? kl : ql;
                        *(uint32_t*)(PH + base) = pack2bf(h0, h1);
                        *(uint32_t*)(PL + base) = pack2bf(l0, l1);
                    } else {
                        const size_t base = (size_t)(bb*16 + h) * (SEQ*HDIM)
                                          + (size_t)d * SEQ + n;
                        vh[base]       = h0;  vh[base + SEQ] = h1;
                        vl[base]       = l0;  vl[base + SEQ] = l1;
                    }
                }
            }
        }
    }
}

// ---------------------------------------------------------------------------
// k2: flash attention FA2 layout: 128 thr, 4 warps; warp w owns query rows
// [w*16, w*16+16) x ALL 64 keys. Softmax fully warp-local (register m/l).
// K double-buffered, V single-buffered, P register-resident (PRMT split).
// smem: Qa 16K | Ka[2] 32K | Va 16K = 65536 B. Target 3 CTAs/SM.
// ---------------------------------------------------------------------------
#define FLASH_SMEM 65536

__global__ void __launch_bounds__(128, 3)
flash_mma_kernel(const __nv_bfloat16* __restrict__ qhi, const __nv_bfloat16* __restrict__ qlo,
                 const __nv_bfloat16* __restrict__ khi, const __nv_bfloat16* __restrict__ klo,
                 const __nv_bfloat16* __restrict__ vhiT, const __nv_bfloat16* __restrict__ vloT,
                 __nv_bfloat16* __restrict__ atta)
{
    extern __shared__ __align__(1024) uint8_t fsm[];
    const uint32_t sbase = smem_u32(fsm);
    const uint32_t qa_u  = sbase;
    const uint32_t ka_u0 = sbase + 16384;    // + buf*16384
    const uint32_t va_u  = sbase + 49152;

    const int tid  = threadIdx.x;
    const int w    = tid >> 5;      // warp: query rows w*16..w*16+15
    const int lane = tid & 31;
    const int g  = lane >> 2;
    const int qd = lane & 3;
    const int rlo = lane & 15, hi = lane >> 4;

    const int qt = blockIdx.x, bh = blockIdx.y;
    const int q0 = qt * 64;

    // Q load (group 1)
    {
        const size_t qbase = ((size_t)bh * SEQ + q0) * HDIM;
        for (int i = tid; i < 1024; i += 128) {
            const int r = i >> 4, c = i & 15;
            CP_ASYNC16(qa_u + foff(r, c),
                       (c < 8 ? qhi : qlo) + qbase + r * HDIM + (c & 7) * 8);
        }
        CP_COMMIT();
    }

    auto load_k = [&](int kt, int buf) {
        const size_t kbase = ((size_t)bh * SEQ + kt * 64) * HDIM;
        const uint32_t ka = ka_u0 + buf * 16384;
        for (int i = tid; i < 1024; i += 128) {
            const int r = i >> 4, c = i & 15;
            CP_ASYNC16(ka + foff(r, c),
                       (c < 8 ? khi : klo) + kbase + r * HDIM + (c & 7) * 8);
        }
    };
    auto load_v = [&](int kt) {
        for (int i = tid; i < 1024; i += 128) {
            const int r = i >> 4, c = i & 15;
            CP_ASYNC16(va_u + foff(r, c),
                       (c < 8 ? vhiT : vloT) + (size_t)(bh * HDIM + r) * SEQ
                                             + kt * 64 + (c & 7) * 8);
        }
    };

    load_k(0, 0); CP_COMMIT();               // group 2

    float m_r[2] = { -1e30f, -1e30f };
    float l_r[2] = { 0.f, 0.f };
    float oacc[8][4] = {};                   // [d-tile][reg], 16 rows x 64 d

    for (int kt = 0; kt < 32; ++kt) {
        const int buf = kt & 1;
        __syncthreads();              // (a) prior iter done with Va / Ka[buf^1]
        load_v(kt); CP_COMMIT();
        if (kt + 1 < 32) load_k(kt + 1, buf ^ 1);
        CP_COMMIT();                  // uniform ledger (possibly empty group)
        CP_WAIT2();                   // K(kt) (and Q on iter 0) landed
        __syncthreads();              // (b) everyone's K(kt) visible

        const uint32_t ka_u = ka_u0 + buf * 16384;

        // ---- S = Qhi.Khi + Qlo.Khi + Qhi.Klo (16 rows x 64 keys/warp) ----
        float sacc[8][4] = {};
        #pragma unroll
        for (int u = 0; u < 4; ++u) {
            uint32_t ah[4], al[4], bh_[4][4], bl[4][4];
            ldsm_x4(ah[0], ah[1], ah[2], ah[3],
                    qa_u + foff(w*16 + rlo, 2*u + hi));
            ldsm_x4(al[0], al[1], al[2], al[3],
                    qa_u + foff(w*16 + rlo, 2*(u+4) + hi));
            #pragma unroll
            for (int j = 0; j < 4; ++j) {
                ldsm_x4(bh_[j][0], bh_[j][1], bh_[j][2], bh_[j][3],
                        ka_u + foff(j*16 + rlo, 2*u + hi));
                ldsm_x4(bl[j][0], bl[j][1], bl[j][2], bl[j][3],
                        ka_u + foff(j*16 + rlo, 2*(u+4) + hi));
            }
            #pragma unroll
            for (int j = 0; j < 4; ++j)
                #pragma unroll
                for (int hl = 0; hl < 2; ++hl) {
                    const int nf = j*2 + hl;
                    mma_bf16(sacc[nf], ah[0], ah[1], ah[2], ah[3],
                             bh_[j][hl], bh_[j][2 + hl]);
                    mma_bf16(sacc[nf], al[0], al[1], al[2], al[3],
                             bh_[j][hl], bh_[j][2 + hl]);
                    mma_bf16(sacc[nf], ah[0], ah[1], ah[2], ah[3],
                             bl[j][hl], bl[j][2 + hl]);
                }
        }

        // ---- warp-local softmax (rows w*16+g, w*16+g+8) ----
        float tmax[2] = { -1e30f, -1e30f };
        #pragma unroll
        for (int nf = 0; nf < 8; ++nf) {
            tmax[0] = fmaxf(tmax[0], fmaxf(sacc[nf][0], sacc[nf][1]));
            tmax[1] = fmaxf(tmax[1], fmaxf(sacc[nf][2], sacc[nf][3]));
        }
        #pragma unroll
        for (int o = 1; o <= 2; o <<= 1) {
            tmax[0] = fmaxf(tmax[0], __shfl_xor_sync(0xffffffffu, tmax[0], o));
            tmax[1] = fmaxf(tmax[1], __shfl_xor_sync(0xffffffffu, tmax[1], o));
        }
        float corr[2], tsum[2] = { 0.f, 0.f };
        float mn[2];
        #pragma unroll
        for (int gg = 0; gg < 2; ++gg) {
            mn[gg] = fmaxf(m_r[gg], tmax[gg]);
            corr[gg] = exp2f(m_r[gg] - mn[gg]);
        }
        #pragma unroll
        for (int nf = 0; nf < 8; ++nf) {
            sacc[nf][0] = exp2f(sacc[nf][0] - mn[0]);
            sacc[nf][1] = exp2f(sacc[nf][1] - mn[0]);
            sacc[nf][2] = exp2f(sacc[nf][2] - mn[1]);
            sacc[nf][3] = exp2f(sacc[nf][3] - mn[1]);
            tsum[0] += sacc[nf][0] + sacc[nf][1];
            tsum[1] += sacc[nf][2] + sacc[nf][3];
        }
        #pragma unroll
        for (int o = 1; o <= 2; o <<= 1) {
            tsum[0] += __shfl_xor_sync(0xffffffffu, tsum[0], o);
            tsum[1] += __shfl_xor_sync(0xffffffffu, tsum[1], o);
        }
        #pragma unroll
        for (int gg = 0; gg < 2; ++gg) {
            l_r[gg] = l_r[gg] * corr[gg] + tsum[gg];
            m_r[gg] = mn[gg];
        }
        #pragma unroll
        for (int nf = 0; nf < 8; ++nf) {
            oacc[nf][0] *= corr[0];
            oacc[nf][1] *= corr[0];
            oacc[nf][2] *= corr[1];
            oacc[nf][3] *= corr[1];
        }

        CP_WAIT1();                   // V(kt) landed (K(kt+1) may still fly)
        __syncthreads();              // (c) everyone's V(kt) visible

        // ---- PV: O += Phi.Vhi + Plo.Vhi + Phi.Vlo (keys ku*16, all 64 d) ----
        #pragma unroll
        for (int ku = 0; ku < 4; ++ku) {
            uint32_t phi[4], plo[4];
            {
                const int nf0 = 2*ku, nf1 = 2*ku + 1;
                phi[0] = prmt_hi(sacc[nf0][0], sacc[nf0][1]);
                phi[1] = prmt_hi(sacc[nf0][2], sacc[nf0][3]);
                phi[2] = prmt_hi(sacc[nf1][0], sacc[nf1][1]);
                phi[3] = prmt_hi(sacc[nf1][2], sacc[nf1][3]);
                plo[0] = prmt_hi(trunc_res(sacc[nf0][0]), trunc_res(sacc[nf0][1]));
                plo[1] = prmt_hi(trunc_res(sacc[nf0][2]), trunc_res(sacc[nf0][3]));
                plo[2] = prmt_hi(trunc_res(sacc[nf1][0]), trunc_res(sacc[nf1][1]));
                plo[3] = prmt_hi(trunc_res(sacc[nf1][2]), trunc_res(sacc[nf1][3]));
            }
            #pragma unroll
            for (int dj = 0; dj < 4; ++dj) {
                uint32_t vh_[4], vl_[4];
                ldsm_x4(vh_[0], vh_[1], vh_[2], vh_[3],
                        va_u + foff(dj*16 + rlo, 2*ku + hi));
                ldsm_x4(vl_[0], vl_[1], vl_[2], vl_[3],
                        va_u + foff(dj*16 + rlo, 2*(ku+4) + hi));
                #pragma unroll
                for (int hl = 0; hl < 2; ++hl) {
                    const int nf_o = dj*2 + hl;
                    mma_bf16(oacc[nf_o], phi[0], phi[1], phi[2], phi[3],
                             vh_[hl], vh_[2 + hl]);
                    mma_bf16(oacc[nf_o], plo[0], plo[1], plo[2], plo[3],
                             vh_[hl], vh_[2 + hl]);
                    mma_bf16(oacc[nf_o], phi[0], phi[1], phi[2], phi[3],
                             vl_[hl], vl_[2 + hl]);
                }
            }
        }
    }

    // ---- epilogue: warp-local normalize + write augmented atta ----
    const int b_ = bh >> 4, h = bh & 15;
    float inv[2] = { 1.f / l_r[0], 1.f / l_r[1] };
    #pragma unroll
    for (int nf = 0; nf < 8; ++nf)
        #pragma unroll
        for (int gg = 0; gg < 2; ++gg) {
            const int r = w*16 + g + gg*8;
            const float v0 = oacc[nf][gg*2]   * inv[gg];
            const float v1 = oacc[nf][gg*2+1] * inv[gg];
            __nv_bfloat16 h0,l0,h1,l1;
            split_hl(v0, h0, l0);
            split_hl(v1, h1, l1);
            const size_t ro = (size_t)(b_*SEQ + q0 + r) * KAUG + h*64 + nf*8 + qd*2;
            *(uint32_t*)(atta + ro)            = pack2bf(h0, h1);
            *(uint32_t*)(atta + ro + EMBED)    = pack2bf(l0, l1);
            *(uint32_t*)(atta + ro + 2*EMBED)  = pack2bf(h0, h1);
        }
}

// ---------------------------------------------------------------------------
// Launch
// ---------------------------------------------------------------------------
extern "C" void kernel_launch(void* const* d_in, const int* in_sizes, int n_in,
                              void* d_out, int out_size)
{
    const float* x      = (const float*)d_in[0];
    const float* w_qkv  = (const float*)d_in[1];
    const float* b_qkv  = (const float*)d_in[2];
    const float* w_proj = (const float*)d_in[3];
    const float* b_proj = (const float*)d_in[4];
    float* out = (float*)d_out;

    __nv_bfloat16 *xa, *atta, *wqkvT, *wprojT, *qh, *ql, *kh, *kl, *vh, *vl;
    cudaGetSymbolAddress((void**)&xa,     g_xa);
    cudaGetSymbolAddress((void**)&atta,   g_atta);
    cudaGetSymbolAddress((void**)&wqkvT,  g_wqkvT);
    cudaGetSymbolAddress((void**)&wprojT, g_wprojT);
    cudaGetSymbolAddress((void**)&qh,     g_qhi);
    cudaGetSymbolAddress((void**)&ql,     g_qlo);
    cudaGetSymbolAddress((void**)&kh,     g_khi);
    cudaGetSymbolAddress((void**)&kl,     g_klo);
    cudaGetSymbolAddress((void**)&vh,     g_vhiT);
    cudaGetSymbolAddress((void**)&vl,     g_vloT);

    cudaFuncSetAttribute(mma_gemm_kernel<1>,
                         cudaFuncAttributeMaxDynamicSharedMemorySize, GEMM_SMEM);
    cudaFuncSetAttribute(mma_gemm_kernel<0>,
                         cudaFuncAttributeMaxDynamicSharedMemorySize, GEMM_SMEM);
    cudaFuncSetAttribute(flash_mma_kernel,
                         cudaFuncAttributeMaxDynamicSharedMemorySize, FLASH_SMEM);

    split_x_kernel<<<MROWS, 256>>>(x, xa);
    transpose_split_kernel<<<dim3(QKV_N/32, EMBED/32), dim3(32,8)>>>(w_qkv, wqkvT, EMBED, QKV_N);
    transpose_split_kernel<<<dim3(EMBED/32, EMBED/32), dim3(32,8)>>>(w_proj, wprojT, EMBED, EMBED);

    mma_gemm_kernel<1><<<dim3(QKV_N/128, MROWS/128), 256, GEMM_SMEM>>>(
        xa, wqkvT, b_qkv, nullptr, qh, ql, kh, kl, vh, vl, MROWS, QKV_N, KAUG);

    flash_mma_kernel<<<dim3(SEQ/64, NBH), 128, FLASH_SMEM>>>(qh, ql, kh, kl, vh, vl, atta);

    mma_gemm_kernel<0><<<dim3(EMBED/128, MROWS/128), 256, GEMM_SMEM>>>(
        atta, wprojT, b_proj, out, nullptr, nullptr, nullptr, nullptr, nullptr, nullptr,
        MROWS, EMBED, KAUG);
}

// round 15
// speedup vs baseline: 1.5852x; 1.3644x over previous
#include <cuda_runtime.h>
#include <cuda_bf16.h>
#include <cuda_fp16.h>
#include <cstdint>

// ===========================================================================
// MultiHeadSelfAttention, sm_100 (mma.sync HMMA path everywhere).
//   s1: split x -> xa bf16 [8192 x 3072] ([hi|lo|hi])
//   s2/s3: transpose+split weights -> [N x 3K] bf16 ([hi|hi|lo])
//   k1: qkv GEMM (split-bf16, BK=32, 4-stage cp.async) -> SINGLE fp16 planes
//       qf/kf [bh][n][64] (Q pre-scaled), vfT [bh][d][n].
//   k2: flash attention in single fp16 (error ~4e-4, under 1e-3 gate):
//       FA2 warp-per-16-rows, warp-local softmax, register P, 4 CTAs/SM.
//       Writes augmented split-bf16 atta for k3.
//   k3: out = atta @ wprojT^T + b_proj (split-bf16).
// ===========================================================================

#define EMBED   1024
#define HEADS   16
#define HDIM    64
#define BATCH   4
#define SEQ     2048
#define MROWS   (BATCH * SEQ)     // 8192
#define QKV_N   (3 * EMBED)       // 3072
#define KAUG    (3 * EMBED)       // 3072
#define NBH     (BATCH * HEADS)   // 64
#define QSC     (0.125f * 1.44269504f)

__device__ __nv_bfloat16  g_xa[(size_t)MROWS * KAUG];       // 48 MB
__device__ __nv_bfloat16  g_atta[(size_t)MROWS * KAUG];     // 48 MB
__device__ __nv_bfloat16  g_wqkvT[(size_t)QKV_N * KAUG];    // 18 MB
__device__ __nv_bfloat16  g_wprojT[(size_t)EMBED * KAUG];   //  6 MB
__device__ __half         g_qf[(size_t)NBH * SEQ * HDIM];   // 16 MB
__device__ __half         g_kf[(size_t)NBH * SEQ * HDIM];   // 16 MB
__device__ __half         g_vfT[(size_t)NBH * HDIM * SEQ];  // 16 MB

// ---------------------------------------------------------------------------
// helpers
// ---------------------------------------------------------------------------
__device__ __forceinline__ uint32_t smem_u32(const void* p) {
    uint32_t a;
    asm("{ .reg .u64 t; cvta.to.shared.u64 t, %1; cvt.u32.u64 %0, t; }"
        : "=r"(a) : "l"(p));
    return a;
}
__device__ __forceinline__ void ldsm_x4(uint32_t& r0, uint32_t& r1,
                                        uint32_t& r2, uint32_t& r3, uint32_t addr) {
    asm volatile("ldmatrix.sync.aligned.m8n8.x4.shared.b16 {%0,%1,%2,%3}, [%4];"
                 : "=r"(r0), "=r"(r1), "=r"(r2), "=r"(r3) : "r"(addr));
}
__device__ __forceinline__ void mma_bf16(float* c, uint32_t a0, uint32_t a1,
                                         uint32_t a2, uint32_t a3,
                                         uint32_t b0, uint32_t b1) {
    asm volatile(
        "mma.sync.aligned.m16n8k16.row.col.f32.bf16.bf16.f32 "
        "{%0,%1,%2,%3}, {%4,%5,%6,%7}, {%8,%9}, {%0,%1,%2,%3};"
        : "+f"(c[0]), "+f"(c[1]), "+f"(c[2]), "+f"(c[3])
        : "r"(a0), "r"(a1), "r"(a2), "r"(a3), "r"(b0), "r"(b1));
}
__device__ __forceinline__ void mma_f16(float* c, uint32_t a0, uint32_t a1,
                                        uint32_t a2, uint32_t a3,
                                        uint32_t b0, uint32_t b1) {
    asm volatile(
        "mma.sync.aligned.m16n8k16.row.col.f32.f16.f16.f32 "
        "{%0,%1,%2,%3}, {%4,%5,%6,%7}, {%8,%9}, {%0,%1,%2,%3};"
        : "+f"(c[0]), "+f"(c[1]), "+f"(c[2]), "+f"(c[3])
        : "r"(a0), "r"(a1), "r"(a2), "r"(a3), "r"(b0), "r"(b1));
}
#define CP_ASYNC16(smem, gptr) \
    asm volatile("cp.async.cg.shared.global [%0], [%1], 16;" :: "r"(smem), "l"(gptr))
#define CP_COMMIT() asm volatile("cp.async.commit_group;" ::: "memory")
#define CP_WAIT1()  asm volatile("cp.async.wait_group 1;" ::: "memory")
#define CP_WAIT2()  asm volatile("cp.async.wait_group 2;" ::: "memory")

// GEMM tile (64B rows): chunk' = chunk ^ ((row>>1)&3)
__device__ __forceinline__ uint32_t tile_off(int r, int c) {
    return (uint32_t)(r * 64 + ((c ^ ((r >> 1) & 3)) << 4));
}
// fp16 flash tile (128B rows, 8 chunks): chunk' = chunk ^ (row & 7)
__device__ __forceinline__ uint32_t hoff(int r, int c) {
    return (uint32_t)(r * 128 + ((c ^ (r & 7)) << 4));
}

__device__ __forceinline__ void split_hl(float v, __nv_bfloat16& hi, __nv_bfloat16& lo) {
    hi = __float2bfloat16_rn(v);
    lo = __float2bfloat16_rn(v - __bfloat162float(hi));
}
__device__ __forceinline__ uint32_t pack2bf(__nv_bfloat16 a, __nv_bfloat16 b) {
    __nv_bfloat162 p(a, b);
    return *reinterpret_cast<uint32_t*>(&p);
}
__device__ __forceinline__ uint32_t f2h2(float a, float b) {
    __half2 h = __floats2half2_rn(a, b);
    return *reinterpret_cast<uint32_t*>(&h);
}

// ---------------------------------------------------------------------------
// s1: split x -> xa [hi | lo | hi]
// ---------------------------------------------------------------------------
__global__ void __launch_bounds__(256)
split_x_kernel(const float* __restrict__ x, __nv_bfloat16* __restrict__ xa)
{
    const int row = blockIdx.x;
    const int c = threadIdx.x * 4;
    float4 v = *(const float4*)(x + (size_t)row * EMBED + c);
    __nv_bfloat16 h0,h1,h2,h3,l0,l1,l2,l3;
    split_hl(v.x, h0, l0); split_hl(v.y, h1, l1);
    split_hl(v.z, h2, l2); split_hl(v.w, h3, l3);
    const size_t o = (size_t)row * KAUG + c;
    uint2 uh; uh.x = pack2bf(h0,h1); uh.y = pack2bf(h2,h3);
    uint2 ul; ul.x = pack2bf(l0,l1); ul.y = pack2bf(l2,l3);
    *(uint2*)(xa + o)           = uh;
    *(uint2*)(xa + o + EMBED)   = ul;
    *(uint2*)(xa + o + 2*EMBED) = uh;
}

// ---------------------------------------------------------------------------
// s2/s3: W [K x N] fp32 -> Bp [N x 3K] bf16 ([hi | hi | lo])
// ---------------------------------------------------------------------------
__global__ void __launch_bounds__(256)
transpose_split_kernel(const float* __restrict__ W, __nv_bfloat16* __restrict__ Bp,
                       int K, int N)
{
    __shared__ float t[32][33];
    const int n0 = blockIdx.x * 32, k0 = blockIdx.y * 32;
    const int tx = threadIdx.x, ty = threadIdx.y;
    #pragma unroll
    for (int i = 0; i < 4; ++i)
        t[ty + 8*i][tx] = W[(size_t)(k0 + ty + 8*i) * N + n0 + tx];
    __syncthreads();
    #pragma unroll
    for (int i = 0; i < 4; ++i) {
        const int n = ty + 8*i;
        float v = t[tx][n];
        __nv_bfloat16 hi, lo;
        split_hl(v, hi, lo);
        const size_t ro = (size_t)(n0 + n) * (3*K);
        Bp[ro + k0 + tx]       = hi;
        Bp[ro + K + k0 + tx]   = hi;
        Bp[ro + 2*K + k0 + tx] = lo;
    }
}

// ---------------------------------------------------------------------------
// HMMA GEMM: 128x128x32 tile, 8 warps (2x4), 4-stage cp.async. 64KB smem.
// MODE 0: C = A@B^T + bias.  MODE 1: qkv epilogue -> fp16 planes qf/kf/vfT.
// ---------------------------------------------------------------------------
#define GEMM_SMEM 65536

template<int MODE>
__global__ void __launch_bounds__(256)
mma_gemm_kernel(const __nv_bfloat16* __restrict__ A, const __nv_bfloat16* __restrict__ B,
                const float* __restrict__ bias, float* __restrict__ C,
                __half* __restrict__ qf, __half* __restrict__ kf,
                __half* __restrict__ vf,
                int M, int N, int K)
{
    extern __shared__ __align__(1024) uint8_t dsm[];

    const int tid  = threadIdx.x;
    const int wid  = tid >> 5;
    const int lane = tid & 31;
    const int bx = blockIdx.x, by = blockIdx.y;
    const int warp_m = wid & 1;
    const int warp_n = wid >> 1;
    const uint32_t sbase = smem_u32(dsm);

    const size_t Ks = (size_t)K;
    const __nv_bfloat16* Ab = A + (size_t)(by * 128) * Ks;
    const __nv_bfloat16* Bb = B + (size_t)(bx * 128) * Ks;

    const int lr0 = tid >> 2,         lc0 = tid & 3;
    const int lr1 = (tid + 256) >> 2, lc1 = (tid + 256) & 3;
    const __nv_bfloat16* Ag0 = Ab + (size_t)lr0 * Ks + lc0 * 8;
    const __nv_bfloat16* Ag1 = Ab + (size_t)lr1 * Ks + lc1 * 8;
    const __nv_bfloat16* Bg0 = Bb + (size_t)lr0 * Ks + lc0 * 8;
    const __nv_bfloat16* Bg1 = Bb + (size_t)lr1 * Ks + lc1 * 8;
    const uint32_t sA0 = tile_off(lr0, lc0), sA1 = tile_off(lr1, lc1);

    auto load_stage = [&](int kt, int st) {
        const int k0 = kt * 32;
        const uint32_t s = sbase + st * 16384;
        CP_ASYNC16(s + sA0,        Ag0 + k0);
        CP_ASYNC16(s + sA1,        Ag1 + k0);
        CP_ASYNC16(s + 8192 + sA0, Bg0 + k0);
        CP_ASYNC16(s + 8192 + sA1, Bg1 + k0);
    };

    uint32_t aoff[2][4], boff[2][2];
    #pragma unroll
    for (int ks = 0; ks < 2; ++ks) {
        #pragma unroll
        for (int mf = 0; mf < 4; ++mf)
            aoff[ks][mf] = tile_off(warp_m * 64 + mf * 16 + (lane & 15),
                                    ks * 2 + (lane >> 4));
        #pragma unroll
        for (int np = 0; np < 2; ++np)
            boff[ks][np] = 8192 + tile_off(warp_n * 32 + np * 16 + (lane & 15),
                                           ks * 2 + (lane >> 4));
    }

    float acc[4][4][4] = {};
    const int T = K >> 5;      // 96

    load_stage(0, 0); CP_COMMIT();
    load_stage(1, 1); CP_COMMIT();
    load_stage(2, 2); CP_COMMIT();

    for (int t = 0; t < T; ++t) {
        CP_WAIT2();
        __syncthreads();

        const uint32_t st = sbase + (t & 3) * 16384;
        #pragma unroll
        for (int ks = 0; ks < 2; ++ks) {
            uint32_t a[4][4];
            #pragma unroll
            for (int mf = 0; mf < 4; ++mf)
                ldsm_x4(a[mf][0], a[mf][1], a[mf][2], a[mf][3], st + aoff[ks][mf]);
            uint32_t b[2][4];
            #pragma unroll
            for (int np = 0; np < 2; ++np)
                ldsm_x4(b[np][0], b[np][1], b[np][2], b[np][3], st + boff[ks][np]);
            #pragma unroll
            for (int mf = 0; mf < 4; ++mf)
                #pragma unroll
                for (int nf = 0; nf < 4; ++nf) {
                    const int np = nf >> 1, hl = nf & 1;
                    mma_bf16(acc[mf][nf], a[mf][0], a[mf][1], a[mf][2], a[mf][3],
                             b[np][0 + hl], b[np][2 + hl]);
                }
        }

        if (t + 3 < T) load_stage(t + 3, (t + 3) & 3);
        CP_COMMIT();
    }

    const int g  = lane >> 2;
    const int cl = (lane & 3) * 2;
    #pragma unroll
    for (int mf = 0; mf < 4; ++mf) {
        const int mrow = by * 128 + warp_m * 64 + mf * 16 + g;
        #pragma unroll
        for (int nf = 0; nf < 4; ++nf) {
            const int col = bx * 128 + warp_n * 32 + nf * 8 + cl;
            const float b0 = bias[col], b1 = bias[col + 1];
            float v[4] = { acc[mf][nf][0] + b0, acc[mf][nf][1] + b1,
                           acc[mf][nf][2] + b0, acc[mf][nf][3] + b1 };
            if constexpr (MODE == 0) {
                *(float2*)(C + (size_t)mrow * N + col)       = make_float2(v[0], v[1]);
                *(float2*)(C + (size_t)(mrow + 8) * N + col) = make_float2(v[2], v[3]);
            } else {
                const int which = col >> 10;           // 0=q 1=k 2=v
                const int h = (col >> 6) & 15;
                const int d = col & 63;
                const int bb = mrow >> 11;
                const int n0 = mrow & 2047;
                if (which == 0) { v[0]*=QSC; v[1]*=QSC; v[2]*=QSC; v[3]*=QSC; }
                #pragma unroll
                for (int rr = 0; rr < 2; ++rr) {
                    const int n = n0 + rr * 8;
                    if (which < 2) {
                        __half* P = which ? kf : qf;
                        const size_t base = (size_t)(bb*16 + h) * (SEQ*HDIM)
                                          + (size_t)n * HDIM + d;
                        *(uint32_t*)(P + base) = f2h2(v[rr*2+0], v[rr*2+1]);
                    } else {
                        const size_t base = (size_t)(bb*16 + h) * (HDIM*SEQ)
                                          + (size_t)d * SEQ + n;
                        vf[base]       = __float2half(v[rr*2+0]);
                        vf[base + SEQ] = __float2half(v[rr*2+1]);
                    }
                }
            }
        }
    }
}

// ---------------------------------------------------------------------------
// k2: flash attention, single fp16, FA2 layout. 128 thr, 4 warps; warp w owns
// query rows [w*16, w*16+16) x all 64 keys. Warp-local softmax, register P.
// smem: Qf 8K | Kf[2] 16K | Vf 8K = 32768 B. Target 4 CTAs/SM.
// ---------------------------------------------------------------------------
#define FLASH_SMEM 32768

__global__ void __launch_bounds__(128, 4)
flash_mma_kernel(const __half* __restrict__ qf, const __half* __restrict__ kf,
                 const __half* __restrict__ vfT,
                 __nv_bfloat16* __restrict__ atta)
{
    extern __shared__ __align__(1024) uint8_t fsm[];
    const uint32_t sbase = smem_u32(fsm);
    const uint32_t qa_u  = sbase;
    const uint32_t ka_u0 = sbase + 8192;     // + buf*8192
    const uint32_t va_u  = sbase + 24576;

    const int tid  = threadIdx.x;
    const int w    = tid >> 5;
    const int lane = tid & 31;
    const int g  = lane >> 2;
    const int qd = lane & 3;
    const int rlo = lane & 15, hi = lane >> 4;

    const int qt = blockIdx.x, bh = blockIdx.y;
    const int q0 = qt * 64;

    // Q load (group 1): 64x64 fp16 = 512 chunks
    {
        const size_t qbase = ((size_t)bh * SEQ + q0) * HDIM;
        for (int i = tid; i < 512; i += 128) {
            const int r = i >> 3, c = i & 7;
            CP_ASYNC16(qa_u + hoff(r, c), qf + qbase + r * HDIM + c * 8);
        }
        CP_COMMIT();
    }

    auto load_k = [&](int kt, int buf) {
        const size_t kbase = ((size_t)bh * SEQ + kt * 64) * HDIM;
        const uint32_t ka = ka_u0 + buf * 8192;
        for (int i = tid; i < 512; i += 128) {
            const int r = i >> 3, c = i & 7;
            CP_ASYNC16(ka + hoff(r, c), kf + kbase + r * HDIM + c * 8);
        }
    };
    auto load_v = [&](int kt) {
        for (int i = tid; i < 512; i += 128) {
            const int r = i >> 3, c = i & 7;
            CP_ASYNC16(va_u + hoff(r, c),
                       vfT + (size_t)(bh * HDIM + r) * SEQ + kt * 64 + c * 8);
        }
    };

    load_k(0, 0); CP_COMMIT();               // group 2

    float m_r[2] = { -1e30f, -1e30f };
    float l_r[2] = { 0.f, 0.f };
    float oacc[8][4] = {};

    for (int kt = 0; kt < 32; ++kt) {
        const int buf = kt & 1;
        __syncthreads();              // (a) prior iter done with Vf / Kf[buf^1]
        load_v(kt); CP_COMMIT();
        if (kt + 1 < 32) load_k(kt + 1, buf ^ 1);
        CP_COMMIT();                  // uniform ledger
        CP_WAIT2();                   // K(kt) (and Q on iter 0) landed
        __syncthreads();              // (b) everyone's K(kt) visible

        const uint32_t ka_u = ka_u0 + buf * 8192;

        // ---- S = Q @ K^T (fp16, 16 rows x 64 keys per warp) ----
        float sacc[8][4] = {};
        #pragma unroll
        for (int u = 0; u < 4; ++u) {
            uint32_t a[4], b[4][4];
            ldsm_x4(a[0], a[1], a[2], a[3],
                    qa_u + hoff(w*16 + rlo, 2*u + hi));
            #pragma unroll
            for (int j = 0; j < 4; ++j)
                ldsm_x4(b[j][0], b[j][1], b[j][2], b[j][3],
                        ka_u + hoff(j*16 + rlo, 2*u + hi));
            #pragma unroll
            for (int j = 0; j < 4; ++j)
                #pragma unroll
                for (int hl = 0; hl < 2; ++hl)
                    mma_f16(sacc[j*2 + hl], a[0], a[1], a[2], a[3],
                            b[j][hl], b[j][2 + hl]);
        }

        // ---- warp-local softmax ----
        float tmax[2] = { -1e30f, -1e30f };
        #pragma unroll
        for (int nf = 0; nf < 8; ++nf) {
            tmax[0] = fmaxf(tmax[0], fmaxf(sacc[nf][0], sacc[nf][1]));
            tmax[1] = fmaxf(tmax[1], fmaxf(sacc[nf][2], sacc[nf][3]));
        }
        #pragma unroll
        for (int o = 1; o <= 2; o <<= 1) {
            tmax[0] = fmaxf(tmax[0], __shfl_xor_sync(0xffffffffu, tmax[0], o));
            tmax[1] = fmaxf(tmax[1], __shfl_xor_sync(0xffffffffu, tmax[1], o));
        }
        float corr[2], tsum[2] = { 0.f, 0.f }, mn[2];
        #pragma unroll
        for (int gg = 0; gg < 2; ++gg) {
            mn[gg] = fmaxf(m_r[gg], tmax[gg]);
            corr[gg] = exp2f(m_r[gg] - mn[gg]);
        }
        #pragma unroll
        for (int nf = 0; nf < 8; ++nf) {
            sacc[nf][0] = exp2f(sacc[nf][0] - mn[0]);
            sacc[nf][1] = exp2f(sacc[nf][1] - mn[0]);
            sacc[nf][2] = exp2f(sacc[nf][2] - mn[1]);
            sacc[nf][3] = exp2f(sacc[nf][3] - mn[1]);
            tsum[0] += sacc[nf][0] + sacc[nf][1];
            tsum[1] += sacc[nf][2] + sacc[nf][3];
        }
        #pragma unroll
        for (int o = 1; o <= 2; o <<= 1) {
            tsum[0] += __shfl_xor_sync(0xffffffffu, tsum[0], o);
            tsum[1] += __shfl_xor_sync(0xffffffffu, tsum[1], o);
        }
        #pragma unroll
        for (int gg = 0; gg < 2; ++gg) {
            l_r[gg] = l_r[gg] * corr[gg] + tsum[gg];
            m_r[gg] = mn[gg];
        }
        #pragma unroll
        for (int nf = 0; nf < 8; ++nf) {
            oacc[nf][0] *= corr[0];
            oacc[nf][1] *= corr[0];
            oacc[nf][2] *= corr[1];
            oacc[nf][3] *= corr[1];
        }

        CP_WAIT1();                   // V(kt) landed
        __syncthreads();              // (c) everyone's V(kt) visible

        // ---- PV: O += P @ V^T (fp16) ----
        #pragma unroll
        for (int ku = 0; ku < 4; ++ku) {
            uint32_t p[4];
            {
                const int nf0 = 2*ku, nf1 = 2*ku + 1;
                p[0] = f2h2(sacc[nf0][0], sacc[nf0][1]);
                p[1] = f2h2(sacc[nf0][2], sacc[nf0][3]);
                p[2] = f2h2(sacc[nf1][0], sacc[nf1][1]);
                p[3] = f2h2(sacc[nf1][2], sacc[nf1][3]);
            }
            #pragma unroll
            for (int dj = 0; dj < 4; ++dj) {
                uint32_t vv[4];
                ldsm_x4(vv[0], vv[1], vv[2], vv[3],
                        va_u + hoff(dj*16 + rlo, 2*ku + hi));
                #pragma unroll
                for (int hl = 0; hl < 2; ++hl)
                    mma_f16(oacc[dj*2 + hl], p[0], p[1], p[2], p[3],
                            vv[hl], vv[2 + hl]);
            }
        }
    }

    // ---- epilogue: warp-local normalize + write augmented atta ----
    const int b_ = bh >> 4, h = bh & 15;
    float inv[2] = { 1.f / l_r[0], 1.f / l_r[1] };
    #pragma unroll
    for (int nf = 0; nf < 8; ++nf)
        #pragma unroll
        for (int gg = 0; gg < 2; ++gg) {
            const int r = w*16 + g + gg*8;
            const float v0 = oacc[nf][gg*2]   * inv[gg];
            const float v1 = oacc[nf][gg*2+1] * inv[gg];
            __nv_bfloat16 h0,l0,h1,l1;
            split_hl(v0, h0, l0);
            split_hl(v1, h1, l1);
            const size_t ro = (size_t)(b_*SEQ + q0 + r) * KAUG + h*64 + nf*8 + qd*2;
            *(uint32_t*)(atta + ro)            = pack2bf(h0, h1);
            *(uint32_t*)(atta + ro + EMBED)    = pack2bf(l0, l1);
            *(uint32_t*)(atta + ro + 2*EMBED)  = pack2bf(h0, h1);
        }
}

// ---------------------------------------------------------------------------
// Launch
// ---------------------------------------------------------------------------
extern "C" void kernel_launch(void* const* d_in, const int* in_sizes, int n_in,
                              void* d_out, int out_size)
{
    const float* x      = (const float*)d_in[0];
    const float* w_qkv  = (const float*)d_in[1];
    const float* b_qkv  = (const float*)d_in[2];
    const float* w_proj = (const float*)d_in[3];
    const float* b_proj = (const float*)d_in[4];
    float* out = (float*)d_out;

    __nv_bfloat16 *xa, *atta, *wqkvT, *wprojT;
    __half *qf, *kf, *vf;
    cudaGetSymbolAddress((void**)&xa,     g_xa);
    cudaGetSymbolAddress((void**)&atta,   g_atta);
    cudaGetSymbolAddress((void**)&wqkvT,  g_wqkvT);
    cudaGetSymbolAddress((void**)&wprojT, g_wprojT);
    cudaGetSymbolAddress((void**)&qf,     g_qf);
    cudaGetSymbolAddress((void**)&kf,     g_kf);
    cudaGetSymbolAddress((void**)&vf,     g_vfT);

    cudaFuncSetAttribute(mma_gemm_kernel<1>,
                         cudaFuncAttributeMaxDynamicSharedMemorySize, GEMM_SMEM);
    cudaFuncSetAttribute(mma_gemm_kernel<0>,
                         cudaFuncAttributeMaxDynamicSharedMemorySize, GEMM_SMEM);
    cudaFuncSetAttribute(flash_mma_kernel,
                         cudaFuncAttributeMaxDynamicSharedMemorySize, FLASH_SMEM);

    split_x_kernel<<<MROWS, 256>>>(x, xa);
    transpose_split_kernel<<<dim3(QKV_N/32, EMBED/32), dim3(32,8)>>>(w_qkv, wqkvT, EMBED, QKV_N);
    transpose_split_kernel<<<dim3(EMBED/32, EMBED/32), dim3(32,8)>>>(w_proj, wprojT, EMBED, EMBED);

    mma_gemm_kernel<1><<<dim3(QKV_N/128, MROWS/128), 256, GEMM_SMEM>>>(
        xa, wqkvT, b_qkv, nullptr, qf, kf, vf, MROWS, QKV_N, KAUG);

    flash_mma_kernel<<<dim3(SEQ/64, NBH), 128, FLASH_SMEM>>>(qf, kf, vf, atta);

    mma_gemm_kernel<0><<<dim3(EMBED/128, MROWS/128), 256, GEMM_SMEM>>>(
        atta, wprojT, b_proj, out, nullptr, nullptr, nullptr, MROWS, EMBED, KAUG);
}

// round 16
// speedup vs baseline: 2.8273x; 1.7836x over previous
#include <cuda_runtime.h>
#include <cuda_bf16.h>
#include <cuda_fp16.h>
#include <cstdint>

// ===========================================================================
// MultiHeadSelfAttention, sm_100 — full single-fp16 pipeline (fp32 accum).
//   s1: x fp32 -> xf fp16 [8192 x 1024]
//   s2/s3: transpose w -> wqkvT fp16 [3072 x 1024], wprojT fp16 [1024 x 1024]
//   k1: qkv = xf @ wqkvT^T + b (fp16 HMMA, K=1024) -> planes qf/kf (Q scaled),
//       vfT [bh][d][n], all fp16.
//   k2: flash attention fp16 (FA2 warp-per-16-rows, warp-local softmax,
//       register P, K double-buf, V single-buf, 4 CTAs/SM) -> attf fp16.
//   k3: out = attf @ wprojT^T + b_proj (fp16 HMMA, K=1024, fp32 out).
// Error budget: attention ~3e-4 + 2 fp16 GEMMs ~4e-4 each => ~6.4e-4 < 1e-3.
// ===========================================================================

#define EMBED   1024
#define HEADS   16
#define HDIM    64
#define BATCH   4
#define SEQ     2048
#define MROWS   (BATCH * SEQ)     // 8192
#define QKV_N   (3 * EMBED)       // 3072
#define NBH     (BATCH * HEADS)   // 64
#define QSC     (0.125f * 1.44269504f)

__device__ __half  g_xf[(size_t)MROWS * EMBED];      // 16 MB
__device__ __half  g_attf[(size_t)MROWS * EMBED];    // 16 MB
__device__ __half  g_wqkvT[(size_t)QKV_N * EMBED];   //  6 MB
__device__ __half  g_wprojT[(size_t)EMBED * EMBED];  //  2 MB
__device__ __half  g_qf[(size_t)NBH * SEQ * HDIM];   // 16 MB
__device__ __half  g_kf[(size_t)NBH * SEQ * HDIM];   // 16 MB
__device__ __half  g_vfT[(size_t)NBH * HDIM * SEQ];  // 16 MB

// ---------------------------------------------------------------------------
// helpers
// ---------------------------------------------------------------------------
__device__ __forceinline__ uint32_t smem_u32(const void* p) {
    uint32_t a;
    asm("{ .reg .u64 t; cvta.to.shared.u64 t, %1; cvt.u32.u64 %0, t; }"
        : "=r"(a) : "l"(p));
    return a;
}
__device__ __forceinline__ void ldsm_x4(uint32_t& r0, uint32_t& r1,
                                        uint32_t& r2, uint32_t& r3, uint32_t addr) {
    asm volatile("ldmatrix.sync.aligned.m8n8.x4.shared.b16 {%0,%1,%2,%3}, [%4];"
                 : "=r"(r0), "=r"(r1), "=r"(r2), "=r"(r3) : "r"(addr));
}
__device__ __forceinline__ void mma_f16(float* c, uint32_t a0, uint32_t a1,
                                        uint32_t a2, uint32_t a3,
                                        uint32_t b0, uint32_t b1) {
    asm volatile(
        "mma.sync.aligned.m16n8k16.row.col.f32.f16.f16.f32 "
        "{%0,%1,%2,%3}, {%4,%5,%6,%7}, {%8,%9}, {%0,%1,%2,%3};"
        : "+f"(c[0]), "+f"(c[1]), "+f"(c[2]), "+f"(c[3])
        : "r"(a0), "r"(a1), "r"(a2), "r"(a3), "r"(b0), "r"(b1));
}
#define CP_ASYNC16(smem, gptr) \
    asm volatile("cp.async.cg.shared.global [%0], [%1], 16;" :: "r"(smem), "l"(gptr))
#define CP_COMMIT() asm volatile("cp.async.commit_group;" ::: "memory")
#define CP_WAIT1()  asm volatile("cp.async.wait_group 1;" ::: "memory")
#define CP_WAIT2()  asm volatile("cp.async.wait_group 2;" ::: "memory")

// GEMM tile (64B rows): chunk' = chunk ^ ((row>>1)&3)
__device__ __forceinline__ uint32_t tile_off(int r, int c) {
    return (uint32_t)(r * 64 + ((c ^ ((r >> 1) & 3)) << 4));
}
// fp16 flash tile (128B rows, 8 chunks): chunk' = chunk ^ (row & 7)
__device__ __forceinline__ uint32_t hoff(int r, int c) {
    return (uint32_t)(r * 128 + ((c ^ (r & 7)) << 4));
}

__device__ __forceinline__ uint32_t f2h2(float a, float b) {
    __half2 h = __floats2half2_rn(a, b);
    return *reinterpret_cast<uint32_t*>(&h);
}

// ---------------------------------------------------------------------------
// s1: convert x -> fp16
// ---------------------------------------------------------------------------
__global__ void __launch_bounds__(256)
convert_x_kernel(const float* __restrict__ x, __half* __restrict__ xf)
{
    const size_t i = ((size_t)blockIdx.x * 256 + threadIdx.x) * 4;
    float4 v = *(const float4*)(x + i);
    uint2 o;
    o.x = f2h2(v.x, v.y);
    o.y = f2h2(v.z, v.w);
    *(uint2*)(xf + i) = o;
}

// ---------------------------------------------------------------------------
// s2/s3: transpose W [K x N] fp32 -> Bp [N x K] fp16
// ---------------------------------------------------------------------------
__global__ void __launch_bounds__(256)
transpose_kernel(const float* __restrict__ W, __half* __restrict__ Bp,
                 int K, int N)
{
    __shared__ float t[32][33];
    const int n0 = blockIdx.x * 32, k0 = blockIdx.y * 32;
    const int tx = threadIdx.x, ty = threadIdx.y;
    #pragma unroll
    for (int i = 0; i < 4; ++i)
        t[ty + 8*i][tx] = W[(size_t)(k0 + ty + 8*i) * N + n0 + tx];
    __syncthreads();
    #pragma unroll
    for (int i = 0; i < 4; ++i) {
        const int n = ty + 8*i;
        Bp[(size_t)(n0 + n) * K + k0 + tx] = __float2half(t[tx][n]);
    }
}

// ---------------------------------------------------------------------------
// fp16 HMMA GEMM: 128x128x32 tile, 8 warps (2x4), 4-stage cp.async. 64KB smem.
// MODE 0: C = A@B^T + bias (fp32).  MODE 1: qkv epilogue -> fp16 planes.
// ---------------------------------------------------------------------------
#define GEMM_SMEM 65536

template<int MODE>
__global__ void __launch_bounds__(256)
mma_gemm_kernel(const __half* __restrict__ A, const __half* __restrict__ B,
                const float* __restrict__ bias, float* __restrict__ C,
                __half* __restrict__ qf, __half* __restrict__ kf,
                __half* __restrict__ vf,
                int M, int N, int K)
{
    extern __shared__ __align__(1024) uint8_t dsm[];

    const int tid  = threadIdx.x;
    const int wid  = tid >> 5;
    const int lane = tid & 31;
    const int bx = blockIdx.x, by = blockIdx.y;
    const int warp_m = wid & 1;
    const int warp_n = wid >> 1;
    const uint32_t sbase = smem_u32(dsm);

    const size_t Ks = (size_t)K;
    const __half* Ab = A + (size_t)(by * 128) * Ks;
    const __half* Bb = B + (size_t)(bx * 128) * Ks;

    const int lr0 = tid >> 2,         lc0 = tid & 3;
    const int lr1 = (tid + 256) >> 2, lc1 = (tid + 256) & 3;
    const __half* Ag0 = Ab + (size_t)lr0 * Ks + lc0 * 8;
    const __half* Ag1 = Ab + (size_t)lr1 * Ks + lc1 * 8;
    const __half* Bg0 = Bb + (size_t)lr0 * Ks + lc0 * 8;
    const __half* Bg1 = Bb + (size_t)lr1 * Ks + lc1 * 8;
    const uint32_t sA0 = tile_off(lr0, lc0), sA1 = tile_off(lr1, lc1);

    auto load_stage = [&](int kt, int st) {
        const int k0 = kt * 32;
        const uint32_t s = sbase + st * 16384;
        CP_ASYNC16(s + sA0,        Ag0 + k0);
        CP_ASYNC16(s + sA1,        Ag1 + k0);
        CP_ASYNC16(s + 8192 + sA0, Bg0 + k0);
        CP_ASYNC16(s + 8192 + sA1, Bg1 + k0);
    };

    uint32_t aoff[2][4], boff[2][2];
    #pragma unroll
    for (int ks = 0; ks < 2; ++ks) {
        #pragma unroll
        for (int mf = 0; mf < 4; ++mf)
            aoff[ks][mf] = tile_off(warp_m * 64 + mf * 16 + (lane & 15),
                                    ks * 2 + (lane >> 4));
        #pragma unroll
        for (int np = 0; np < 2; ++np)
            boff[ks][np] = 8192 + tile_off(warp_n * 32 + np * 16 + (lane & 15),
                                           ks * 2 + (lane >> 4));
    }

    float acc[4][4][4] = {};
    const int T = K >> 5;      // 32

    load_stage(0, 0); CP_COMMIT();
    load_stage(1, 1); CP_COMMIT();
    load_stage(2, 2); CP_COMMIT();

    for (int t = 0; t < T; ++t) {
        CP_WAIT2();
        __syncthreads();

        const uint32_t st = sbase + (t & 3) * 16384;
        #pragma unroll
        for (int ks = 0; ks < 2; ++ks) {
            uint32_t a[4][4];
            #pragma unroll
            for (int mf = 0; mf < 4; ++mf)
                ldsm_x4(a[mf][0], a[mf][1], a[mf][2], a[mf][3], st + aoff[ks][mf]);
            uint32_t b[2][4];
            #pragma unroll
            for (int np = 0; np < 2; ++np)
                ldsm_x4(b[np][0], b[np][1], b[np][2], b[np][3], st + boff[ks][np]);
            #pragma unroll
            for (int mf = 0; mf < 4; ++mf)
                #pragma unroll
                for (int nf = 0; nf < 4; ++nf) {
                    const int np = nf >> 1, hl = nf & 1;
                    mma_f16(acc[mf][nf], a[mf][0], a[mf][1], a[mf][2], a[mf][3],
                            b[np][0 + hl], b[np][2 + hl]);
                }
        }

        if (t + 3 < T) load_stage(t + 3, (t + 3) & 3);
        CP_COMMIT();
    }

    const int g  = lane >> 2;
    const int cl = (lane & 3) * 2;
    #pragma unroll
    for (int mf = 0; mf < 4; ++mf) {
        const int mrow = by * 128 + warp_m * 64 + mf * 16 + g;
        #pragma unroll
        for (int nf = 0; nf < 4; ++nf) {
            const int col = bx * 128 + warp_n * 32 + nf * 8 + cl;
            const float b0 = bias[col], b1 = bias[col + 1];
            float v[4] = { acc[mf][nf][0] + b0, acc[mf][nf][1] + b1,
                           acc[mf][nf][2] + b0, acc[mf][nf][3] + b1 };
            if constexpr (MODE == 0) {
                *(float2*)(C + (size_t)mrow * N + col)       = make_float2(v[0], v[1]);
                *(float2*)(C + (size_t)(mrow + 8) * N + col) = make_float2(v[2], v[3]);
            } else {
                const int which = col >> 10;           // 0=q 1=k 2=v
                const int h = (col >> 6) & 15;
                const int d = col & 63;
                const int bb = mrow >> 11;
                const int n0 = mrow & 2047;
                if (which == 0) { v[0]*=QSC; v[1]*=QSC; v[2]*=QSC; v[3]*=QSC; }
                #pragma unroll
                for (int rr = 0; rr < 2; ++rr) {
                    const int n = n0 + rr * 8;
                    if (which < 2) {
                        __half* P = which ? kf : qf;
                        const size_t base = (size_t)(bb*16 + h) * (SEQ*HDIM)
                                          + (size_t)n * HDIM + d;
                        *(uint32_t*)(P + base) = f2h2(v[rr*2+0], v[rr*2+1]);
                    } else {
                        const size_t base = (size_t)(bb*16 + h) * (HDIM*SEQ)
                                          + (size_t)d * SEQ + n;
                        vf[base]       = __float2half(v[rr*2+0]);
                        vf[base + SEQ] = __float2half(v[rr*2+1]);
                    }
                }
            }
        }
    }
}

// ---------------------------------------------------------------------------
// k2: flash attention, single fp16, FA2 layout. 128 thr, 4 warps; warp w owns
// query rows [w*16, w*16+16) x all 64 keys. Warp-local softmax, register P.
// smem: Qf 8K | Kf[2] 16K | Vf 8K = 32768 B. 4 CTAs/SM.
// ---------------------------------------------------------------------------
#define FLASH_SMEM 32768

__global__ void __launch_bounds__(128, 4)
flash_mma_kernel(const __half* __restrict__ qf, const __half* __restrict__ kf,
                 const __half* __restrict__ vfT,
                 __half* __restrict__ attf)
{
    extern __shared__ __align__(1024) uint8_t fsm[];
    const uint32_t sbase = smem_u32(fsm);
    const uint32_t qa_u  = sbase;
    const uint32_t ka_u0 = sbase + 8192;     // + buf*8192
    const uint32_t va_u  = sbase + 24576;

    const int tid  = threadIdx.x;
    const int w    = tid >> 5;
    const int lane = tid & 31;
    const int g  = lane >> 2;
    const int qd = lane & 3;
    const int rlo = lane & 15, hi = lane >> 4;

    const int qt = blockIdx.x, bh = blockIdx.y;
    const int q0 = qt * 64;

    // Q load (group 1)
    {
        const size_t qbase = ((size_t)bh * SEQ + q0) * HDIM;
        for (int i = tid; i < 512; i += 128) {
            const int r = i >> 3, c = i & 7;
            CP_ASYNC16(qa_u + hoff(r, c), qf + qbase + r * HDIM + c * 8);
        }
        CP_COMMIT();
    }

    auto load_k = [&](int kt, int buf) {
        const size_t kbase = ((size_t)bh * SEQ + kt * 64) * HDIM;
        const uint32_t ka = ka_u0 + buf * 8192;
        for (int i = tid; i < 512; i += 128) {
            const int r = i >> 3, c = i & 7;
            CP_ASYNC16(ka + hoff(r, c), kf + kbase + r * HDIM + c * 8);
        }
    };
    auto load_v = [&](int kt) {
        for (int i = tid; i < 512; i += 128) {
            const int r = i >> 3, c = i & 7;
            CP_ASYNC16(va_u + hoff(r, c),
                       vfT + (size_t)(bh * HDIM + r) * SEQ + kt * 64 + c * 8);
        }
    };

    load_k(0, 0); CP_COMMIT();               // group 2

    float m_r[2] = { -1e30f, -1e30f };
    float l_r[2] = { 0.f, 0.f };
    float oacc[8][4] = {};

    for (int kt = 0; kt < 32; ++kt) {
        const int buf = kt & 1;
        __syncthreads();              // (a) prior iter done with Vf / Kf[buf^1]
        load_v(kt); CP_COMMIT();
        if (kt + 1 < 32) load_k(kt + 1, buf ^ 1);
        CP_COMMIT();                  // uniform ledger
        CP_WAIT2();                   // K(kt) (and Q on iter 0) landed
        __syncthreads();              // (b) everyone's K(kt) visible

        const uint32_t ka_u = ka_u0 + buf * 8192;

        // ---- S = Q @ K^T ----
        float sacc[8][4] = {};
        #pragma unroll
        for (int u = 0; u < 4; ++u) {
            uint32_t a[4], b[4][4];
            ldsm_x4(a[0], a[1], a[2], a[3],
                    qa_u + hoff(w*16 + rlo, 2*u + hi));
            #pragma unroll
            for (int j = 0; j < 4; ++j)
                ldsm_x4(b[j][0], b[j][1], b[j][2], b[j][3],
                        ka_u + hoff(j*16 + rlo, 2*u + hi));
            #pragma unroll
            for (int j = 0; j < 4; ++j)
                #pragma unroll
                for (int hl = 0; hl < 2; ++hl)
                    mma_f16(sacc[j*2 + hl], a[0], a[1], a[2], a[3],
                            b[j][hl], b[j][2 + hl]);
        }

        // ---- warp-local softmax ----
        float tmax[2] = { -1e30f, -1e30f };
        #pragma unroll
        for (int nf = 0; nf < 8; ++nf) {
            tmax[0] = fmaxf(tmax[0], fmaxf(sacc[nf][0], sacc[nf][1]));
            tmax[1] = fmaxf(tmax[1], fmaxf(sacc[nf][2], sacc[nf][3]));
        }
        #pragma unroll
        for (int o = 1; o <= 2; o <<= 1) {
            tmax[0] = fmaxf(tmax[0], __shfl_xor_sync(0xffffffffu, tmax[0], o));
            tmax[1] = fmaxf(tmax[1], __shfl_xor_sync(0xffffffffu, tmax[1], o));
        }
        float corr[2], tsum[2] = { 0.f, 0.f }, mn[2];
        #pragma unroll
        for (int gg = 0; gg < 2; ++gg) {
            mn[gg] = fmaxf(m_r[gg], tmax[gg]);
            corr[gg] = exp2f(m_r[gg] - mn[gg]);
        }
        #pragma unroll
        for (int nf = 0; nf < 8; ++nf) {
            sacc[nf][0] = exp2f(sacc[nf][0] - mn[0]);
            sacc[nf][1] = exp2f(sacc[nf][1] - mn[0]);
            sacc[nf][2] = exp2f(sacc[nf][2] - mn[1]);
            sacc[nf][3] = exp2f(sacc[nf][3] - mn[1]);
            tsum[0] += sacc[nf][0] + sacc[nf][1];
            tsum[1] += sacc[nf][2] + sacc[nf][3];
        }
        #pragma unroll
        for (int o = 1; o <= 2; o <<= 1) {
            tsum[0] += __shfl_xor_sync(0xffffffffu, tsum[0], o);
            tsum[1] += __shfl_xor_sync(0xffffffffu, tsum[1], o);
        }
        #pragma unroll
        for (int gg = 0; gg < 2; ++gg) {
            l_r[gg] = l_r[gg] * corr[gg] + tsum[gg];
            m_r[gg] = mn[gg];
        }
        #pragma unroll
        for (int nf = 0; nf < 8; ++nf) {
            oacc[nf][0] *= corr[0];
            oacc[nf][1] *= corr[0];
            oacc[nf][2] *= corr[1];
            oacc[nf][3] *= corr[1];
        }

        CP_WAIT1();                   // V(kt) landed
        __syncthreads();              // (c) everyone's V(kt) visible

        // ---- PV: O += P @ V^T ----
        #pragma unroll
        for (int ku = 0; ku < 4; ++ku) {
            uint32_t p[4];
            {
                const int nf0 = 2*ku, nf1 = 2*ku + 1;
                p[0] = f2h2(sacc[nf0][0], sacc[nf0][1]);
                p[1] = f2h2(sacc[nf0][2], sacc[nf0][3]);
                p[2] = f2h2(sacc[nf1][0], sacc[nf1][1]);
                p[3] = f2h2(sacc[nf1][2], sacc[nf1][3]);
            }
            #pragma unroll
            for (int dj = 0; dj < 4; ++dj) {
                uint32_t vv[4];
                ldsm_x4(vv[0], vv[1], vv[2], vv[3],
                        va_u + hoff(dj*16 + rlo, 2*ku + hi));
                #pragma unroll
                for (int hl = 0; hl < 2; ++hl)
                    mma_f16(oacc[dj*2 + hl], p[0], p[1], p[2], p[3],
                            vv[hl], vv[2 + hl]);
            }
        }
    }

    // ---- epilogue: warp-local normalize + write single fp16 attf ----
    const int b_ = bh >> 4, h = bh & 15;
    float inv[2] = { 1.f / l_r[0], 1.f / l_r[1] };
    #pragma unroll
    for (int nf = 0; nf < 8; ++nf)
        #pragma unroll
        for (int gg = 0; gg < 2; ++gg) {
            const int r = w*16 + g + gg*8;
            const float v0 = oacc[nf][gg*2]   * inv[gg];
            const float v1 = oacc[nf][gg*2+1] * inv[gg];
            const size_t ro = (size_t)(b_*SEQ + q0 + r) * EMBED + h*64 + nf*8 + qd*2;
            *(uint32_t*)(attf + ro) = f2h2(v0, v1);
        }
}

// ---------------------------------------------------------------------------
// Launch
// ---------------------------------------------------------------------------
extern "C" void kernel_launch(void* const* d_in, const int* in_sizes, int n_in,
                              void* d_out, int out_size)
{
    const float* x      = (const float*)d_in[0];
    const float* w_qkv  = (const float*)d_in[1];
    const float* b_qkv  = (const float*)d_in[2];
    const float* w_proj = (const float*)d_in[3];
    const float* b_proj = (const float*)d_in[4];
    float* out = (float*)d_out;

    __half *xf, *attf, *wqkvT, *wprojT, *qf, *kf, *vf;
    cudaGetSymbolAddress((void**)&xf,     g_xf);
    cudaGetSymbolAddress((void**)&attf,   g_attf);
    cudaGetSymbolAddress((void**)&wqkvT,  g_wqkvT);
    cudaGetSymbolAddress((void**)&wprojT, g_wprojT);
    cudaGetSymbolAddress((void**)&qf,     g_qf);
    cudaGetSymbolAddress((void**)&kf,     g_kf);
    cudaGetSymbolAddress((void**)&vf,     g_vfT);

    cudaFuncSetAttribute(mma_gemm_kernel<1>,
                         cudaFuncAttributeMaxDynamicSharedMemorySize, GEMM_SMEM);
    cudaFuncSetAttribute(mma_gemm_kernel<0>,
                         cudaFuncAttributeMaxDynamicSharedMemorySize, GEMM_SMEM);
    cudaFuncSetAttribute(flash_mma_kernel,
                         cudaFuncAttributeMaxDynamicSharedMemorySize, FLASH_SMEM);

    convert_x_kernel<<<MROWS * EMBED / 1024, 256>>>(x, xf);
    transpose_kernel<<<dim3(QKV_N/32, EMBED/32), dim3(32,8)>>>(w_qkv, wqkvT, EMBED, QKV_N);
    transpose_kernel<<<dim3(EMBED/32, EMBED/32), dim3(32,8)>>>(w_proj, wprojT, EMBED, EMBED);

    mma_gemm_kernel<1><<<dim3(QKV_N/128, MROWS/128), 256, GEMM_SMEM>>>(
        xf, wqkvT, b_qkv, nullptr, qf, kf, vf, MROWS, QKV_N, EMBED);

    flash_mma_kernel<<<dim3(SEQ/64, NBH), 128, FLASH_SMEM>>>(qf, kf, vf, attf);

    mma_gemm_kernel<0><<<dim3(EMBED/128, MROWS/128), 256, GEMM_SMEM>>>(
        attf, wprojT, b_proj, out, nullptr, nullptr, nullptr, MROWS, EMBED, EMBED);
}